// round 6
// baseline (speedup 1.0000x reference)
#include <cuda_runtime.h>

typedef unsigned long long ull;

#define NS   2048
#define NB   4
#define NH   8
#define NBH  32        // NB*NH
#define NROWS 8192     // NB*NS

// -------- scratch (static __device__ arrays; no allocation allowed) --------
__device__ float g_Q[NBH * NS * 16];   // [b,h,s,j], Q pre-scaled by 1/sqrt(128)
__device__ float g_K[NBH * NS * 16];
__device__ float g_V[NBH * NS * 16];
__device__ float g_O[NBH * NS * 16];   // attention output per head
__device__ float g_LWT[128 * 128];     // lin_w transposed: LWT[d][c] = lin_w[c][d]

// buggy concat order kept faithful to the reference
__constant__ int c_ord[8] = {0, 1, 1, 2, 3, 4, 5, 6};

// -------- packed f32x2 helpers (sm_103a dual-FMA) --------
__device__ __forceinline__ ull ffma2(ull a, ull b, ull c) {
    ull d;
    asm("fma.rn.f32x2 %0, %1, %2, %3;" : "=l"(d) : "l"(a), "l"(b), "l"(c));
    return d;
}
__device__ __forceinline__ ull fmul2(ull a, ull b) {
    ull d;
    asm("mul.rn.f32x2 %0, %1, %2;" : "=l"(d) : "l"(a), "l"(b));
    return d;
}
__device__ __forceinline__ ull pk2(float x, float y) {
    ull r;
    asm("mov.b64 %0, {%1, %2};" : "=l"(r)
        : "r"(__float_as_uint(x)), "r"(__float_as_uint(y)));
    return r;
}
__device__ __forceinline__ float2 upk2(ull a) {
    unsigned lo, hi;
    asm("mov.b64 {%0, %1}, %2;" : "=r"(lo), "=r"(hi) : "l"(a));
    return make_float2(__uint_as_float(lo), __uint_as_float(hi));
}

// ============================================================================
// Kernel 1: fused QKV projection.  q = X @ W  (W row-major [128][128]).
// Block: 256 threads computes 64 rows x 128 cols. grid = (128, 3).
// Output layout: [b, h, s, j] (head-split), Q scaled by 1/sqrt(128).
// ============================================================================
__global__ __launch_bounds__(256) void qkv_kernel(
    const float* __restrict__ X,
    const float* __restrict__ Wq,
    const float* __restrict__ Wk,
    const float* __restrict__ Wv)
{
    __shared__ float Xs[64][128];
    int which = blockIdx.y;
    const float* W = (which == 0) ? Wq : ((which == 1) ? Wk : Wv);
    float* out = (which == 0) ? g_Q : ((which == 1) ? g_K : g_V);
    float scale = (which == 0) ? 0.08838834764831845f : 1.0f;  // 1/sqrt(128)

    int row0 = blockIdx.x * 64;
    const float4* X4 = (const float4*)(X + row0 * 128);
    float4* Xs4 = (float4*)&Xs[0][0];
#pragma unroll
    for (int i = 0; i < 8; i++)
        Xs4[threadIdx.x + i * 256] = X4[threadIdx.x + i * 256];
    __syncthreads();

    int c4 = threadIdx.x & 31;   // float4 column group: cols c4*4 .. c4*4+3
    int rg = threadIdx.x >> 5;   // row group: rows rg*8 .. rg*8+7

    float4 acc[8];
#pragma unroll
    for (int i = 0; i < 8; i++) acc[i] = make_float4(0.f, 0.f, 0.f, 0.f);

    const float4* W4 = (const float4*)W;
    for (int d0 = 0; d0 < 128; d0 += 4) {
        float4 w0 = W4[(d0 + 0) * 32 + c4];
        float4 w1 = W4[(d0 + 1) * 32 + c4];
        float4 w2 = W4[(d0 + 2) * 32 + c4];
        float4 w3 = W4[(d0 + 3) * 32 + c4];
#pragma unroll
        for (int i = 0; i < 8; i++) {
            float4 a = *(const float4*)&Xs[rg * 8 + i][d0];
            acc[i].x = fmaf(a.x, w0.x, fmaf(a.y, w1.x, fmaf(a.z, w2.x, fmaf(a.w, w3.x, acc[i].x))));
            acc[i].y = fmaf(a.x, w0.y, fmaf(a.y, w1.y, fmaf(a.z, w2.y, fmaf(a.w, w3.y, acc[i].y))));
            acc[i].z = fmaf(a.x, w0.z, fmaf(a.y, w1.z, fmaf(a.z, w2.z, fmaf(a.w, w3.z, acc[i].z))));
            acc[i].w = fmaf(a.x, w0.w, fmaf(a.y, w1.w, fmaf(a.z, w2.w, fmaf(a.w, w3.w, acc[i].w))));
        }
    }

    int col = c4 * 4;
    int h = col >> 4;
    int j = col & 15;
#pragma unroll
    for (int i = 0; i < 8; i++) {
        int row = row0 + rg * 8 + i;
        int b = row >> 11;          // row / 2048
        int s = row & 2047;
        float4 v = acc[i];
        v.x *= scale; v.y *= scale; v.z *= scale; v.w *= scale;
        *(float4*)&out[(((b * 8 + h) * NS + s) * 16) + j] = v;
    }
}

// ============================================================================
// Kernel 2: transpose lin_w  ->  g_LWT[d][c] = lin_w[c][d]
// ============================================================================
__global__ void prep_kernel(const float* __restrict__ lw) {
    int t = blockIdx.x * 256 + threadIdx.x;
    if (t < 128 * 128) {
        int d = t >> 7, c = t & 127;
        g_LWT[t] = lw[c * 128 + d];
    }
}

// ============================================================================
// Kernel 3: flash attention.  One query row per thread.
// grid = (16, 32): blockIdx.x = query tile (128 rows), blockIdx.y = (b,h).
// Online softmax over key tiles of 32; packed f32x2 FMA throughout.
// ============================================================================
__global__ __launch_bounds__(128) void attn_kernel(const int* __restrict__ mask) {
    __shared__ float4 KV[256];   // [0..127] = K tile (32 keys x 16f), [128..255] = V tile
    __shared__ float bs[32];     // key bias: -1000 (masked) / 0

    int bh = blockIdx.y;
    int b = bh >> 3;
    int r = blockIdx.x * 128 + threadIdx.x;   // query row

    const float* Qr = g_Q + (bh * NS + r) * 16;
    ull q2[8];
    {
        const longlong2* Q2 = (const longlong2*)Qr;
#pragma unroll
        for (int i = 0; i < 4; i++) {
            longlong2 t = Q2[i];
            q2[2 * i] = (ull)t.x;
            q2[2 * i + 1] = (ull)t.y;
        }
    }

    float m = -1e30f, l = 0.f;
    ull o2[8];
#pragma unroll
    for (int i = 0; i < 8; i++) o2[i] = 0ull;

    const float4* Kb = (const float4*)(g_K + bh * NS * 16);
    const float4* Vb = (const float4*)(g_V + bh * NS * 16);
    const int* mrow = mask + b * NS;

    for (int kt = 0; kt < NS; kt += 32) {
        KV[threadIdx.x]       = Kb[kt * 4 + threadIdx.x];
        KV[128 + threadIdx.x] = Vb[kt * 4 + threadIdx.x];
        if (threadIdx.x < 32)
            bs[threadIdx.x] = (mrow[kt + threadIdx.x] == 0) ? -1000.f : 0.f;
        __syncthreads();

        float sv[32];
#pragma unroll
        for (int j = 0; j < 32; j++) {
            const longlong2* kj = (const longlong2*)&KV[j * 4];
            longlong2 k0 = kj[0], k1 = kj[1];
            ull a0 = fmul2(q2[0], (ull)k0.x);
            ull a1 = fmul2(q2[1], (ull)k0.y);
            a0 = ffma2(q2[2], (ull)k1.x, a0);
            a1 = ffma2(q2[3], (ull)k1.y, a1);
            longlong2 k2 = kj[2], k3 = kj[3];
            a0 = ffma2(q2[4], (ull)k2.x, a0);
            a1 = ffma2(q2[5], (ull)k2.y, a1);
            a0 = ffma2(q2[6], (ull)k3.x, a0);
            a1 = ffma2(q2[7], (ull)k3.y, a1);
            float2 u = upk2(a0), v = upk2(a1);
            sv[j] = (u.x + u.y) + (v.x + v.y) + bs[j];
        }

        float tm = sv[0];
#pragma unroll
        for (int j = 1; j < 32; j++) tm = fmaxf(tm, sv[j]);
        float mnew = fmaxf(m, tm);
        float corr = __expf(m - mnew);    // -> 0 on first tile (m = -1e30)
        l *= corr;
        ull c2 = pk2(corr, corr);
#pragma unroll
        for (int i = 0; i < 8; i++) o2[i] = fmul2(o2[i], c2);
        m = mnew;

#pragma unroll
        for (int j = 0; j < 32; j++) {
            float p = __expf(sv[j] - mnew);
            l += p;
            ull p2 = pk2(p, p);
            const longlong2* vj = (const longlong2*)&KV[128 + j * 4];
            longlong2 v0 = vj[0], v1 = vj[1];
            o2[0] = ffma2(p2, (ull)v0.x, o2[0]);
            o2[1] = ffma2(p2, (ull)v0.y, o2[1]);
            o2[2] = ffma2(p2, (ull)v1.x, o2[2]);
            o2[3] = ffma2(p2, (ull)v1.y, o2[3]);
            longlong2 v2 = vj[2], v3 = vj[3];
            o2[4] = ffma2(p2, (ull)v2.x, o2[4]);
            o2[5] = ffma2(p2, (ull)v2.y, o2[5]);
            o2[6] = ffma2(p2, (ull)v3.x, o2[6]);
            o2[7] = ffma2(p2, (ull)v3.y, o2[7]);
        }
        __syncthreads();
    }

    float inv = 1.0f / l;
    float4* Or4 = (float4*)(g_O + (bh * NS + r) * 16);
#pragma unroll
    for (int i = 0; i < 4; i++) {
        float2 a = upk2(o2[2 * i]);
        float2 bq = upk2(o2[2 * i + 1]);
        Or4[i] = make_float4(a.x * inv, a.y * inv, bq.x * inv, bq.y * inv);
    }
}

// ============================================================================
// Kernel 4: output projection.  y = attn_out @ lin_w^T + bias
// attn_out built on the fly from g_O with the buggy HEAD_ORDER gather.
// Same tiling as qkv_kernel. grid = 128, 256 threads.
// ============================================================================
__global__ __launch_bounds__(256) void proj_kernel(
    const float* __restrict__ bias, float* __restrict__ out)
{
    __shared__ float Xs[64][128];
    int row0 = blockIdx.x * 64;

#pragma unroll
    for (int ii = 0; ii < 8; ii++) {
        int i = threadIdx.x + ii * 256;     // float4 index in [0, 2048)
        int rr = i >> 5, cc4 = i & 31;
        int row = row0 + rr;
        int b = row >> 11, s = row & 2047;
        int col = cc4 * 4;
        int hh = c_ord[col >> 4];
        int j = col & 15;
        *(float4*)&Xs[rr][col] =
            *(const float4*)&g_O[(((b * 8 + hh) * NS + s) * 16) + j];
    }
    __syncthreads();

    int c4 = threadIdx.x & 31;
    int rg = threadIdx.x >> 5;

    float4 bb = ((const float4*)bias)[c4];
    float4 acc[8];
#pragma unroll
    for (int i = 0; i < 8; i++) acc[i] = bb;

    const float4* W4 = (const float4*)g_LWT;
    for (int d0 = 0; d0 < 128; d0 += 4) {
        float4 w0 = W4[(d0 + 0) * 32 + c4];
        float4 w1 = W4[(d0 + 1) * 32 + c4];
        float4 w2 = W4[(d0 + 2) * 32 + c4];
        float4 w3 = W4[(d0 + 3) * 32 + c4];
#pragma unroll
        for (int i = 0; i < 8; i++) {
            float4 a = *(const float4*)&Xs[rg * 8 + i][d0];
            acc[i].x = fmaf(a.x, w0.x, fmaf(a.y, w1.x, fmaf(a.z, w2.x, fmaf(a.w, w3.x, acc[i].x))));
            acc[i].y = fmaf(a.x, w0.y, fmaf(a.y, w1.y, fmaf(a.z, w2.y, fmaf(a.w, w3.y, acc[i].y))));
            acc[i].z = fmaf(a.x, w0.z, fmaf(a.y, w1.z, fmaf(a.z, w2.z, fmaf(a.w, w3.z, acc[i].z))));
            acc[i].w = fmaf(a.x, w0.w, fmaf(a.y, w1.w, fmaf(a.z, w2.w, fmaf(a.w, w3.w, acc[i].w))));
        }
    }

#pragma unroll
    for (int i = 0; i < 8; i++) {
        int row = row0 + rg * 8 + i;
        ((float4*)out)[row * 32 + c4] = acc[i];
    }
}

// ============================================================================
extern "C" void kernel_launch(void* const* d_in, const int* in_sizes, int n_in,
                              void* d_out, int out_size) {
    const float* X    = (const float*)d_in[0];
    const int*   mask = (const int*)d_in[1];   // token_attention_masks (0/1)
    const float* Wq   = (const float*)d_in[2];
    const float* Wk   = (const float*)d_in[3];
    const float* Wv   = (const float*)d_in[4];
    const float* lw   = (const float*)d_in[5];
    const float* lb   = (const float*)d_in[6];
    float* out = (float*)d_out;

    qkv_kernel<<<dim3(128, 3), 256>>>(X, Wq, Wk, Wv);
    prep_kernel<<<64, 256>>>(lw);
    attn_kernel<<<dim3(16, 32), 128>>>(mask);
    proj_kernel<<<128, 256>>>(lb, out);
}

// round 11
// speedup vs baseline: 1.6035x; 1.6035x over previous
#include <cuda_runtime.h>

typedef unsigned long long ull;

#define NS   2048
#define NB   4
#define NH   8
#define NBH  32        // NB*NH
#define NROWS 8192     // NB*NS

// -------- scratch (static __device__ arrays; no allocation allowed) --------
__device__ float g_Q[NBH * NS * 16];   // [b,h,s,j], Q pre-scaled by log2(e)/sqrt(128)
__device__ float g_K[NBH * NS * 16];
__device__ float g_V[NBH * NS * 16];
__device__ float g_O[NBH * NS * 16];   // attention output per head
__device__ float g_LWT[128 * 128];     // lin_w transposed
__device__ int   g_cnt[NB];            // compacted (unmasked) key count per batch
__device__ int   g_list[NB][NS];       // compacted key indices per batch

// buggy concat order kept faithful to the reference
__constant__ int c_ord[8] = {0, 1, 1, 2, 3, 4, 5, 6};

// -------- packed f32x2 + fast exp2 helpers --------
__device__ __forceinline__ ull ffma2(ull a, ull b, ull c) {
    ull d;
    asm("fma.rn.f32x2 %0, %1, %2, %3;" : "=l"(d) : "l"(a), "l"(b), "l"(c));
    return d;
}
__device__ __forceinline__ ull fmul2(ull a, ull b) {
    ull d;
    asm("mul.rn.f32x2 %0, %1, %2;" : "=l"(d) : "l"(a), "l"(b));
    return d;
}
__device__ __forceinline__ ull pk2(float x, float y) {
    ull r;
    asm("mov.b64 %0, {%1, %2};" : "=l"(r)
        : "r"(__float_as_uint(x)), "r"(__float_as_uint(y)));
    return r;
}
__device__ __forceinline__ float2 upk2(ull a) {
    unsigned lo, hi;
    asm("mov.b64 {%0, %1}, %2;" : "=r"(lo), "=r"(hi) : "l"(a));
    return make_float2(__uint_as_float(lo), __uint_as_float(hi));
}
__device__ __forceinline__ float ex2(float x) {
    float y;
    asm("ex2.approx.ftz.f32 %0, %1;" : "=f"(y) : "f"(x));
    return y;
}

// ============================================================================
// Kernel 1: fused QKV projection. 32 rows/block, grid (256, 3).
// Output layout: [b,h,s,j]; Q pre-scaled by log2(e)/sqrt(128) (exp2 folding).
// ============================================================================
__global__ __launch_bounds__(256) void qkv_kernel(
    const float* __restrict__ X,
    const float* __restrict__ Wq,
    const float* __restrict__ Wk,
    const float* __restrict__ Wv)
{
    __shared__ float Xs[32][128];
    int which = blockIdx.y;
    const float* W = (which == 0) ? Wq : ((which == 1) ? Wk : Wv);
    float* out = (which == 0) ? g_Q : ((which == 1) ? g_K : g_V);
    // Q gets 1/sqrt(128) * log2(e) folded in
    float scale = (which == 0) ? (0.08838834764831845f * 1.4426950408889634f) : 1.0f;

    int row0 = blockIdx.x * 32;
    const float4* X4 = (const float4*)(X + row0 * 128);
    float4* Xs4 = (float4*)&Xs[0][0];
#pragma unroll
    for (int i = 0; i < 4; i++)
        Xs4[threadIdx.x + i * 256] = X4[threadIdx.x + i * 256];
    __syncthreads();

    int c4 = threadIdx.x & 31;   // float4 column group
    int rg = threadIdx.x >> 5;   // row group: rows rg*4 .. rg*4+3

    float4 acc[4];
#pragma unroll
    for (int i = 0; i < 4; i++) acc[i] = make_float4(0.f, 0.f, 0.f, 0.f);

    const float4* W4 = (const float4*)W;
    for (int d0 = 0; d0 < 128; d0 += 4) {
        float4 w0 = W4[(d0 + 0) * 32 + c4];
        float4 w1 = W4[(d0 + 1) * 32 + c4];
        float4 w2 = W4[(d0 + 2) * 32 + c4];
        float4 w3 = W4[(d0 + 3) * 32 + c4];
#pragma unroll
        for (int i = 0; i < 4; i++) {
            float4 a = *(const float4*)&Xs[rg * 4 + i][d0];
            acc[i].x = fmaf(a.x, w0.x, fmaf(a.y, w1.x, fmaf(a.z, w2.x, fmaf(a.w, w3.x, acc[i].x))));
            acc[i].y = fmaf(a.x, w0.y, fmaf(a.y, w1.y, fmaf(a.z, w2.y, fmaf(a.w, w3.y, acc[i].y))));
            acc[i].z = fmaf(a.x, w0.z, fmaf(a.y, w1.z, fmaf(a.z, w2.z, fmaf(a.w, w3.z, acc[i].z))));
            acc[i].w = fmaf(a.x, w0.w, fmaf(a.y, w1.w, fmaf(a.z, w2.w, fmaf(a.w, w3.w, acc[i].w))));
        }
    }

    int col = c4 * 4;
    int h = col >> 4;
    int j = col & 15;
#pragma unroll
    for (int i = 0; i < 4; i++) {
        int row = row0 + rg * 4 + i;
        int b = row >> 11;
        int s = row & 2047;
        float4 v = acc[i];
        v.x *= scale; v.y *= scale; v.z *= scale; v.w *= scale;
        *(float4*)&out[(((b * 8 + h) * NS + s) * 16) + j] = v;
    }
}

// ============================================================================
// Kernel 2a: transpose lin_w
// ============================================================================
__global__ void prep_kernel(const float* __restrict__ lw) {
    int t = blockIdx.x * 256 + threadIdx.x;
    if (t < 128 * 128) {
        int d = t >> 7, c = t & 127;
        g_LWT[t] = lw[c * 128 + d];
    }
}

// ============================================================================
// Kernel 2b: deterministic key compaction (one warp per batch).
// mask bias is -1000 -> expf underflows to exactly 0 in fp32 in the
// reference, so masked keys contribute nothing. Skip them entirely.
// ============================================================================
__global__ void compact_kernel(const int* __restrict__ mask) {
    int b = blockIdx.x;
    int lane = threadIdx.x;
    const int* m = mask + b * NS;
    int base = 0;
    for (int k0 = 0; k0 < NS; k0 += 32) {
        int v = (m[k0 + lane] != 0);
        unsigned bal = __ballot_sync(0xffffffffu, v);
        int pos = base + __popc(bal & ((1u << lane) - 1u));
        if (v) g_list[b][pos] = k0 + lane;
        base += __popc(bal);
    }
    if (base == 0) {
        // all keys masked: constant bias cancels in softmax -> attend to all
        for (int i = lane; i < NS; i += 32) g_list[b][i] = i;
        base = NS;
    }
    // pad to multiple of 16 with index 0 (masked out via cnt check in attn)
    int padded = (base + 15) & ~15;
    for (int i = base + lane; i < padded; i += 32) g_list[b][i] = 0;
    if (lane == 0) g_cnt[b] = base;
}

// ============================================================================
// Kernel 3: flash attention over COMPACTED keys. 1 query/thread,
// grid (16, 32), 128 threads. Key tiles of 16. exp2-domain (scale pre-folded).
// No bias anywhere: every compacted key is unmasked.
// ============================================================================
__global__ __launch_bounds__(128) void attn_kernel() {
    __shared__ float4 KV[128];   // [0..63] K tile (16 keys x 16f), [64..127] V tile
    __shared__ int lst[NS];
    __shared__ int s_cnt;

    int bh = blockIdx.y;
    int b = bh >> 3;
    int tid = threadIdx.x;

    if (tid == 0) s_cnt = g_cnt[b];
    for (int i = tid; i < NS; i += 128) lst[i] = g_list[b][i];
    __syncthreads();
    int cnt = s_cnt;
    int ntiles = (cnt + 15) >> 4;

    int r = blockIdx.x * 128 + tid;
    ull q2[8];
    {
        const longlong2* Q2 = (const longlong2*)(g_Q + ((size_t)bh * NS + r) * 16);
#pragma unroll
        for (int i = 0; i < 4; i++) {
            longlong2 t = Q2[i];
            q2[2 * i] = (ull)t.x;
            q2[2 * i + 1] = (ull)t.y;
        }
    }

    float m = -1e30f, l = 0.f;
    ull o2[8];
#pragma unroll
    for (int i = 0; i < 8; i++) o2[i] = 0ull;

    const float4* Kb = (const float4*)(g_K + (size_t)bh * NS * 16);
    const float4* Vb = (const float4*)(g_V + (size_t)bh * NS * 16);

    for (int t = 0; t < ntiles; t++) {
        int kbase = t << 4;
        {
            int i = tid & 63;
            int row = i >> 2, part = i & 3;
            int kidx = lst[kbase + row];
            const float4* src = (tid < 64) ? (Kb + (size_t)kidx * 4 + part)
                                           : (Vb + (size_t)kidx * 4 + part);
            KV[(tid & 64) + row * 4 + part] = *src;
        }
        __syncthreads();

        float sv[16];
#pragma unroll
        for (int j = 0; j < 16; j++) {
            const longlong2* kj = (const longlong2*)&KV[j * 4];
            longlong2 k0 = kj[0], k1 = kj[1];
            ull a0 = fmul2(q2[0], (ull)k0.x);
            ull a1 = fmul2(q2[1], (ull)k0.y);
            a0 = ffma2(q2[2], (ull)k1.x, a0);
            a1 = ffma2(q2[3], (ull)k1.y, a1);
            longlong2 k2 = kj[2], k3 = kj[3];
            a0 = ffma2(q2[4], (ull)k2.x, a0);
            a1 = ffma2(q2[5], (ull)k2.y, a1);
            a0 = ffma2(q2[6], (ull)k3.x, a0);
            a1 = ffma2(q2[7], (ull)k3.y, a1);
            float2 u = upk2(a0), v = upk2(a1);
            float s = (u.x + u.y) + (v.x + v.y);
            sv[j] = (kbase + j < cnt) ? s : -1e30f;
        }

        float tm = sv[0];
#pragma unroll
        for (int j = 1; j < 16; j++) tm = fmaxf(tm, sv[j]);
        float mnew = fmaxf(m, tm);
        float corr = ex2(m - mnew);     // 0 on first tile
        l *= corr;
        ull c2 = pk2(corr, corr);
#pragma unroll
        for (int i = 0; i < 8; i++) o2[i] = fmul2(o2[i], c2);
        m = mnew;

#pragma unroll
        for (int j = 0; j < 16; j++) {
            float p = ex2(sv[j] - mnew);
            l += p;
            ull p2 = pk2(p, p);
            const longlong2* vj = (const longlong2*)&KV[64 + j * 4];
            longlong2 v0 = vj[0], v1 = vj[1];
            o2[0] = ffma2(p2, (ull)v0.x, o2[0]);
            o2[1] = ffma2(p2, (ull)v0.y, o2[1]);
            o2[2] = ffma2(p2, (ull)v1.x, o2[2]);
            o2[3] = ffma2(p2, (ull)v1.y, o2[3]);
            longlong2 v2 = vj[2], v3 = vj[3];
            o2[4] = ffma2(p2, (ull)v2.x, o2[4]);
            o2[5] = ffma2(p2, (ull)v2.y, o2[5]);
            o2[6] = ffma2(p2, (ull)v3.x, o2[6]);
            o2[7] = ffma2(p2, (ull)v3.y, o2[7]);
        }
        __syncthreads();
    }

    float inv = 1.0f / l;
    float4* Or4 = (float4*)(g_O + ((size_t)bh * NS + r) * 16);
#pragma unroll
    for (int i = 0; i < 4; i++) {
        float2 a = upk2(o2[2 * i]);
        float2 bq = upk2(o2[2 * i + 1]);
        Or4[i] = make_float4(a.x * inv, a.y * inv, bq.x * inv, bq.y * inv);
    }
}

// ============================================================================
// Kernel 4: output projection. 32 rows/block, grid 256. Buggy HEAD_ORDER
// gather done while filling the smem tile.
// ============================================================================
__global__ __launch_bounds__(256) void proj_kernel(
    const float* __restrict__ bias, float* __restrict__ out)
{
    __shared__ float Xs[32][128];
    int row0 = blockIdx.x * 32;

#pragma unroll
    for (int ii = 0; ii < 4; ii++) {
        int i = threadIdx.x + ii * 256;     // float4 index in [0, 1024)
        int rr = i >> 5, cc4 = i & 31;
        int row = row0 + rr;
        int b = row >> 11, s = row & 2047;
        int col = cc4 * 4;
        int hh = c_ord[col >> 4];
        int j = col & 15;
        *(float4*)&Xs[rr][col] =
            *(const float4*)&g_O[(((b * 8 + hh) * NS + s) * 16) + j];
    }
    __syncthreads();

    int c4 = threadIdx.x & 31;
    int rg = threadIdx.x >> 5;

    float4 bb = ((const float4*)bias)[c4];
    float4 acc[4];
#pragma unroll
    for (int i = 0; i < 4; i++) acc[i] = bb;

    const float4* W4 = (const float4*)g_LWT;
    for (int d0 = 0; d0 < 128; d0 += 4) {
        float4 w0 = W4[(d0 + 0) * 32 + c4];
        float4 w1 = W4[(d0 + 1) * 32 + c4];
        float4 w2 = W4[(d0 + 2) * 32 + c4];
        float4 w3 = W4[(d0 + 3) * 32 + c4];
#pragma unroll
        for (int i = 0; i < 4; i++) {
            float4 a = *(const float4*)&Xs[rg * 4 + i][d0];
            acc[i].x = fmaf(a.x, w0.x, fmaf(a.y, w1.x, fmaf(a.z, w2.x, fmaf(a.w, w3.x, acc[i].x))));
            acc[i].y = fmaf(a.x, w0.y, fmaf(a.y, w1.y, fmaf(a.z, w2.y, fmaf(a.w, w3.y, acc[i].y))));
            acc[i].z = fmaf(a.x, w0.z, fmaf(a.y, w1.z, fmaf(a.z, w2.z, fmaf(a.w, w3.z, acc[i].z))));
            acc[i].w = fmaf(a.x, w0.w, fmaf(a.y, w1.w, fmaf(a.z, w2.w, fmaf(a.w, w3.w, acc[i].w))));
        }
    }

#pragma unroll
    for (int i = 0; i < 4; i++) {
        int row = row0 + rg * 4 + i;
        ((float4*)out)[row * 32 + c4] = acc[i];
    }
}

// ============================================================================
extern "C" void kernel_launch(void* const* d_in, const int* in_sizes, int n_in,
                              void* d_out, int out_size) {
    const float* X    = (const float*)d_in[0];
    const int*   mask = (const int*)d_in[1];
    const float* Wq   = (const float*)d_in[2];
    const float* Wk   = (const float*)d_in[3];
    const float* Wv   = (const float*)d_in[4];
    const float* lw   = (const float*)d_in[5];
    const float* lb   = (const float*)d_in[6];
    float* out = (float*)d_out;

    qkv_kernel<<<dim3(256, 3), 256>>>(X, Wq, Wk, Wv);
    prep_kernel<<<64, 256>>>(lw);
    compact_kernel<<<NB, 32>>>(mask);
    attn_kernel<<<dim3(16, 32), 128>>>();
    proj_kernel<<<256, 256>>>(lb, out);
}

// round 12
// speedup vs baseline: 1.8388x; 1.1468x over previous
#include <cuda_runtime.h>

typedef unsigned long long ull;

#define NS   2048
#define NB   4
#define NH   8
#define NBH  32        // NB*NH
#define NROWS 8192     // NB*NS
#define NSPLIT 4
#define NQ   (NBH * NS)   // 65536 total queries

// -------- scratch (static __device__ arrays; no allocation allowed) --------
__device__ float g_Q[NBH * NS * 16];   // [b,h,s,j], Q pre-scaled by log2(e)/sqrt(128)
__device__ float g_K[NBH * NS * 16];
__device__ float g_V[NBH * NS * 16];
__device__ float g_O[NBH * NS * 16];   // attention output per head
__device__ float g_LWT[128 * 128];     // lin_w transposed
__device__ int   g_cnt[NB];            // compacted (unmasked) key count per batch
__device__ int   g_list[NB][NS];       // compacted key indices per batch
__device__ float2 g_Pml[NSPLIT * NQ];      // per-split (m, l)
__device__ float4 g_Po[NSPLIT * NQ * 4];   // per-split unnormalized o (16 floats)

// buggy concat order kept faithful to the reference
__constant__ int c_ord[8] = {0, 1, 1, 2, 3, 4, 5, 6};

// -------- packed f32x2 + fast exp2 helpers --------
__device__ __forceinline__ ull ffma2(ull a, ull b, ull c) {
    ull d;
    asm("fma.rn.f32x2 %0, %1, %2, %3;" : "=l"(d) : "l"(a), "l"(b), "l"(c));
    return d;
}
__device__ __forceinline__ ull fmul2(ull a, ull b) {
    ull d;
    asm("mul.rn.f32x2 %0, %1, %2;" : "=l"(d) : "l"(a), "l"(b));
    return d;
}
__device__ __forceinline__ ull pk2(float x, float y) {
    ull r;
    asm("mov.b64 %0, {%1, %2};" : "=l"(r)
        : "r"(__float_as_uint(x)), "r"(__float_as_uint(y)));
    return r;
}
__device__ __forceinline__ float2 upk2(ull a) {
    unsigned lo, hi;
    asm("mov.b64 {%0, %1}, %2;" : "=r"(lo), "=r"(hi) : "l"(a));
    return make_float2(__uint_as_float(lo), __uint_as_float(hi));
}
__device__ __forceinline__ float ex2(float x) {
    float y;
    asm("ex2.approx.ftz.f32 %0, %1;" : "=f"(y) : "f"(x));
    return y;
}

// ============================================================================
// Kernel 1: fused QKV projection, f32x2-packed. 32 rows/block, grid (256, 3).
// Output layout: [b,h,s,j]; Q pre-scaled by log2(e)/sqrt(128) (exp2 folding).
// ============================================================================
__global__ __launch_bounds__(256) void qkv_kernel(
    const float* __restrict__ X,
    const float* __restrict__ Wq,
    const float* __restrict__ Wk,
    const float* __restrict__ Wv)
{
    __shared__ float Xs[32][128];
    int which = blockIdx.y;
    const float* W = (which == 0) ? Wq : ((which == 1) ? Wk : Wv);
    float* out = (which == 0) ? g_Q : ((which == 1) ? g_K : g_V);
    float scale = (which == 0) ? (0.08838834764831845f * 1.4426950408889634f) : 1.0f;

    int row0 = blockIdx.x * 32;
    const float4* X4 = (const float4*)(X + row0 * 128);
    float4* Xs4 = (float4*)&Xs[0][0];
#pragma unroll
    for (int i = 0; i < 4; i++)
        Xs4[threadIdx.x + i * 256] = X4[threadIdx.x + i * 256];
    __syncthreads();

    int c4 = threadIdx.x & 31;   // float4 column group (cols 4c4..4c4+3)
    int rg = threadIdx.x >> 5;   // row group: rows rg*4 .. rg*4+3

    ull acc01[4], acc23[4];
#pragma unroll
    for (int i = 0; i < 4; i++) { acc01[i] = 0ull; acc23[i] = 0ull; }

    const longlong2* WL = (const longlong2*)W;   // WL[d*32 + c4] = 4 floats of row d
    for (int d0 = 0; d0 < 128; d0 += 4) {
        longlong2 w0 = WL[(d0 + 0) * 32 + c4];
        longlong2 w1 = WL[(d0 + 1) * 32 + c4];
        longlong2 w2 = WL[(d0 + 2) * 32 + c4];
        longlong2 w3 = WL[(d0 + 3) * 32 + c4];
#pragma unroll
        for (int i = 0; i < 4; i++) {
            float4 a = *(const float4*)&Xs[rg * 4 + i][d0];
            ull ax = pk2(a.x, a.x), ay = pk2(a.y, a.y);
            ull az = pk2(a.z, a.z), aw = pk2(a.w, a.w);
            acc01[i] = ffma2(ax, (ull)w0.x, acc01[i]);
            acc23[i] = ffma2(ax, (ull)w0.y, acc23[i]);
            acc01[i] = ffma2(ay, (ull)w1.x, acc01[i]);
            acc23[i] = ffma2(ay, (ull)w1.y, acc23[i]);
            acc01[i] = ffma2(az, (ull)w2.x, acc01[i]);
            acc23[i] = ffma2(az, (ull)w2.y, acc23[i]);
            acc01[i] = ffma2(aw, (ull)w3.x, acc01[i]);
            acc23[i] = ffma2(aw, (ull)w3.y, acc23[i]);
        }
    }

    int col = c4 * 4;
    int h = col >> 4;
    int j = col & 15;
#pragma unroll
    for (int i = 0; i < 4; i++) {
        int row = row0 + rg * 4 + i;
        int b = row >> 11;
        int s = row & 2047;
        float2 lo = upk2(acc01[i]), hi = upk2(acc23[i]);
        float4 v = make_float4(lo.x * scale, lo.y * scale, hi.x * scale, hi.y * scale);
        *(float4*)&out[(((b * 8 + h) * NS + s) * 16) + j] = v;
    }
}

// ============================================================================
// Kernel 2a: transpose lin_w
// ============================================================================
__global__ void prep_kernel(const float* __restrict__ lw) {
    int t = blockIdx.x * 256 + threadIdx.x;
    if (t < 128 * 128) {
        int d = t >> 7, c = t & 127;
        g_LWT[t] = lw[c * 128 + d];
    }
}

// ============================================================================
// Kernel 2b: deterministic key compaction (one warp per batch).
// -1000 bias -> expf underflows to exactly 0 in fp32; masked keys skipped.
// ============================================================================
__global__ void compact_kernel(const int* __restrict__ mask) {
    int b = blockIdx.x;
    int lane = threadIdx.x;
    const int* m = mask + b * NS;
    int base = 0;
    for (int k0 = 0; k0 < NS; k0 += 32) {
        int v = (m[k0 + lane] != 0);
        unsigned bal = __ballot_sync(0xffffffffu, v);
        int pos = base + __popc(bal & ((1u << lane) - 1u));
        if (v) g_list[b][pos] = k0 + lane;
        base += __popc(bal);
    }
    if (base == 0) {
        for (int i = lane; i < NS; i += 32) g_list[b][i] = i;
        base = NS;
    }
    int padded = (base + 15) & ~15;
    for (int i = base + lane; i < padded; i += 32) g_list[b][i] = 0;
    if (lane == 0) g_cnt[b] = base;
}

// ============================================================================
// Kernel 3: flash attention over COMPACTED keys, SPLIT-K x4.
// grid (16, 32, 4): x = query tile (128 rows), y = (b,h), z = key split.
// Writes unnormalized partial (m, l, o) per query per split.
// ============================================================================
__global__ __launch_bounds__(128) void attn_kernel() {
    __shared__ float4 KV[128];   // [0..63] K tile (16 keys x 16f), [64..127] V tile
    __shared__ int lst[512];     // this split's compacted key indices

    int bh = blockIdx.y;
    int b = bh >> 3;
    int sp = blockIdx.z;
    int tid = threadIdx.x;

    int cnt = g_cnt[b];                  // broadcast load
    int ntiles = (cnt + 15) >> 4;
    int tps = (ntiles + NSPLIT - 1) >> 2;
    int t0 = sp * tps;
    int t1 = min(ntiles, t0 + tps);

    int r = blockIdx.x * 128 + tid;
    int pidx = (sp * NBH + bh) * NS + r;

    if (t0 >= t1) {                      // empty split (block-uniform)
        g_Pml[pidx] = make_float2(-1e30f, 0.f);
        float4 z = make_float4(0.f, 0.f, 0.f, 0.f);
        float4* Po = &g_Po[(size_t)pidx * 4];
        Po[0] = z; Po[1] = z; Po[2] = z; Po[3] = z;
        return;
    }

    for (int i = tid; i < (t1 - t0) * 16; i += 128)
        lst[i] = g_list[b][t0 * 16 + i];

    ull q2[8];
    {
        const longlong2* Q2 = (const longlong2*)(g_Q + ((size_t)bh * NS + r) * 16);
#pragma unroll
        for (int i = 0; i < 4; i++) {
            longlong2 t = Q2[i];
            q2[2 * i] = (ull)t.x;
            q2[2 * i + 1] = (ull)t.y;
        }
    }
    __syncthreads();

    float m = -1e30f, l = 0.f;
    ull o2[8];
#pragma unroll
    for (int i = 0; i < 8; i++) o2[i] = 0ull;

    const float4* Kb = (const float4*)(g_K + (size_t)bh * NS * 16);
    const float4* Vb = (const float4*)(g_V + (size_t)bh * NS * 16);

    for (int t = t0; t < t1; t++) {
        int kbase = t << 4;
        {
            int i = tid & 63;
            int row = i >> 2, part = i & 3;
            int kidx = lst[(t - t0) * 16 + row];
            const float4* src = (tid < 64) ? (Kb + (size_t)kidx * 4 + part)
                                           : (Vb + (size_t)kidx * 4 + part);
            KV[(tid & 64) + row * 4 + part] = *src;
        }
        __syncthreads();

        float sv[16];
#pragma unroll
        for (int j = 0; j < 16; j++) {
            const longlong2* kj = (const longlong2*)&KV[j * 4];
            longlong2 k0 = kj[0], k1 = kj[1];
            ull a0 = fmul2(q2[0], (ull)k0.x);
            ull a1 = fmul2(q2[1], (ull)k0.y);
            a0 = ffma2(q2[2], (ull)k1.x, a0);
            a1 = ffma2(q2[3], (ull)k1.y, a1);
            longlong2 k2 = kj[2], k3 = kj[3];
            a0 = ffma2(q2[4], (ull)k2.x, a0);
            a1 = ffma2(q2[5], (ull)k2.y, a1);
            a0 = ffma2(q2[6], (ull)k3.x, a0);
            a1 = ffma2(q2[7], (ull)k3.y, a1);
            float2 u = upk2(a0), v = upk2(a1);
            float s = (u.x + u.y) + (v.x + v.y);
            sv[j] = (kbase + j < cnt) ? s : -1e30f;
        }

        float tm = sv[0];
#pragma unroll
        for (int j = 1; j < 16; j++) tm = fmaxf(tm, sv[j]);
        if (tm > m) {                    // rescale only when max moves (rare later)
            float corr = ex2(m - tm);    // 0 on first tile
            l *= corr;
            ull c2 = pk2(corr, corr);
#pragma unroll
            for (int i = 0; i < 8; i++) o2[i] = fmul2(o2[i], c2);
            m = tm;
        }

#pragma unroll
        for (int j = 0; j < 16; j++) {
            float p = ex2(sv[j] - m);
            l += p;
            ull p2 = pk2(p, p);
            const longlong2* vj = (const longlong2*)&KV[64 + j * 4];
            longlong2 v0 = vj[0], v1 = vj[1];
            o2[0] = ffma2(p2, (ull)v0.x, o2[0]);
            o2[1] = ffma2(p2, (ull)v0.y, o2[1]);
            o2[2] = ffma2(p2, (ull)v1.x, o2[2]);
            o2[3] = ffma2(p2, (ull)v1.y, o2[3]);
            longlong2 v2 = vj[2], v3 = vj[3];
            o2[4] = ffma2(p2, (ull)v2.x, o2[4]);
            o2[5] = ffma2(p2, (ull)v2.y, o2[5]);
            o2[6] = ffma2(p2, (ull)v3.x, o2[6]);
            o2[7] = ffma2(p2, (ull)v3.y, o2[7]);
        }
        __syncthreads();
    }

    g_Pml[pidx] = make_float2(m, l);
    float4* Po = &g_Po[(size_t)pidx * 4];
#pragma unroll
    for (int i = 0; i < 4; i++) {
        float2 a = upk2(o2[2 * i]);
        float2 bq = upk2(o2[2 * i + 1]);
        Po[i] = make_float4(a.x, a.y, bq.x, bq.y);
    }
}

// ============================================================================
// Kernel 3b: combine split-K partials -> g_O. One thread per query.
// ============================================================================
__global__ __launch_bounds__(256) void combine_kernel() {
    int q = blockIdx.x * 256 + threadIdx.x;    // q = bh*NS + r, [0, NQ)

    float2 ml[NSPLIT];
    float M = -1e30f;
#pragma unroll
    for (int s = 0; s < NSPLIT; s++) {
        ml[s] = g_Pml[s * NQ + q];
        M = fmaxf(M, ml[s].x);
    }
    float l = 0.f;
    float4 o0 = make_float4(0, 0, 0, 0), o1 = o0, o2v = o0, o3 = o0;
#pragma unroll
    for (int s = 0; s < NSPLIT; s++) {
        float w = ex2(ml[s].x - M);            // 0 for empty splits
        l += ml[s].y * w;
        const float4* P = &g_Po[((size_t)s * NQ + q) * 4];
        float4 p0 = P[0], p1 = P[1], p2 = P[2], p3 = P[3];
        o0.x += p0.x * w; o0.y += p0.y * w; o0.z += p0.z * w; o0.w += p0.w * w;
        o1.x += p1.x * w; o1.y += p1.y * w; o1.z += p1.z * w; o1.w += p1.w * w;
        o2v.x += p2.x * w; o2v.y += p2.y * w; o2v.z += p2.z * w; o2v.w += p2.w * w;
        o3.x += p3.x * w; o3.y += p3.y * w; o3.z += p3.z * w; o3.w += p3.w * w;
    }
    float inv = 1.0f / l;
    float4* O = (float4*)(g_O + (size_t)q * 16);
    O[0] = make_float4(o0.x * inv, o0.y * inv, o0.z * inv, o0.w * inv);
    O[1] = make_float4(o1.x * inv, o1.y * inv, o1.z * inv, o1.w * inv);
    O[2] = make_float4(o2v.x * inv, o2v.y * inv, o2v.z * inv, o2v.w * inv);
    O[3] = make_float4(o3.x * inv, o3.y * inv, o3.z * inv, o3.w * inv);
}

// ============================================================================
// Kernel 4: output projection, f32x2-packed. 32 rows/block, grid 256.
// Buggy HEAD_ORDER gather done while filling the smem tile.
// ============================================================================
__global__ __launch_bounds__(256) void proj_kernel(
    const float* __restrict__ bias, float* __restrict__ out)
{
    __shared__ float Xs[32][128];
    int row0 = blockIdx.x * 32;

#pragma unroll
    for (int ii = 0; ii < 4; ii++) {
        int i = threadIdx.x + ii * 256;     // float4 index in [0, 1024)
        int rr = i >> 5, cc4 = i & 31;
        int row = row0 + rr;
        int b = row >> 11, s = row & 2047;
        int col = cc4 * 4;
        int hh = c_ord[col >> 4];
        int j = col & 15;
        *(float4*)&Xs[rr][col] =
            *(const float4*)&g_O[(((b * 8 + hh) * NS + s) * 16) + j];
    }
    __syncthreads();

    int c4 = threadIdx.x & 31;
    int rg = threadIdx.x >> 5;

    float4 bb = ((const float4*)bias)[c4];
    ull acc01[4], acc23[4];
#pragma unroll
    for (int i = 0; i < 4; i++) {
        acc01[i] = pk2(bb.x, bb.y);
        acc23[i] = pk2(bb.z, bb.w);
    }

    const longlong2* WL = (const longlong2*)g_LWT;
    for (int d0 = 0; d0 < 128; d0 += 4) {
        longlong2 w0 = WL[(d0 + 0) * 32 + c4];
        longlong2 w1 = WL[(d0 + 1) * 32 + c4];
        longlong2 w2 = WL[(d0 + 2) * 32 + c4];
        longlong2 w3 = WL[(d0 + 3) * 32 + c4];
#pragma unroll
        for (int i = 0; i < 4; i++) {
            float4 a = *(const float4*)&Xs[rg * 4 + i][d0];
            ull ax = pk2(a.x, a.x), ay = pk2(a.y, a.y);
            ull az = pk2(a.z, a.z), aw = pk2(a.w, a.w);
            acc01[i] = ffma2(ax, (ull)w0.x, acc01[i]);
            acc23[i] = ffma2(ax, (ull)w0.y, acc23[i]);
            acc01[i] = ffma2(ay, (ull)w1.x, acc01[i]);
            acc23[i] = ffma2(ay, (ull)w1.y, acc23[i]);
            acc01[i] = ffma2(az, (ull)w2.x, acc01[i]);
            acc23[i] = ffma2(az, (ull)w2.y, acc23[i]);
            acc01[i] = ffma2(aw, (ull)w3.x, acc01[i]);
            acc23[i] = ffma2(aw, (ull)w3.y, acc23[i]);
        }
    }

#pragma unroll
    for (int i = 0; i < 4; i++) {
        int row = row0 + rg * 4 + i;
        float2 lo = upk2(acc01[i]), hi = upk2(acc23[i]);
        ((float4*)out)[row * 32 + c4] = make_float4(lo.x, lo.y, hi.x, hi.y);
    }
}

// ============================================================================
extern "C" void kernel_launch(void* const* d_in, const int* in_sizes, int n_in,
                              void* d_out, int out_size) {
    const float* X    = (const float*)d_in[0];
    const int*   mask = (const int*)d_in[1];
    const float* Wq   = (const float*)d_in[2];
    const float* Wk   = (const float*)d_in[3];
    const float* Wv   = (const float*)d_in[4];
    const float* lw   = (const float*)d_in[5];
    const float* lb   = (const float*)d_in[6];
    float* out = (float*)d_out;

    qkv_kernel<<<dim3(256, 3), 256>>>(X, Wq, Wk, Wv);
    prep_kernel<<<64, 256>>>(lw);
    compact_kernel<<<NB, 32>>>(mask);
    attn_kernel<<<dim3(16, 32, NSPLIT), 128>>>();
    combine_kernel<<<NQ / 256, 256>>>();
    proj_kernel<<<256, 256>>>(lb, out);
}

// round 13
// speedup vs baseline: 2.0621x; 1.1214x over previous
#include <cuda_runtime.h>

typedef unsigned long long ull;

#define NS   2048
#define NB   4
#define NH   8
#define NBH  32        // NB*NH
#define NROWS 8192     // NB*NS
#define NSPLIT 4
#define NQ   (NBH * NS)   // 65536 total queries

// -------- scratch (static __device__ arrays; no allocation allowed) --------
__device__ float g_Q[NBH * NS * 16];   // [b,h,s,j], Q pre-scaled by log2(e)/sqrt(128)
__device__ float g_K[NBH * NS * 16];
__device__ float g_V[NBH * NS * 16];
__device__ float g_O[NBH * NS * 16];   // attention output per head
__device__ float g_LWT[128 * 128];     // lin_w transposed
__device__ int   g_cnt[NB];            // compacted (unmasked) key count per batch
__device__ int   g_list[NB][NS];       // compacted key indices per batch
__device__ float2 g_Pml[NSPLIT * NQ];      // per-split (m, l)
__device__ float4 g_Po[NSPLIT * NQ * 4];   // per-split unnormalized o (16 floats)

// buggy concat order kept faithful to the reference
__constant__ int c_ord[8] = {0, 1, 1, 2, 3, 4, 5, 6};

// -------- packed f32x2 + fast exp2 helpers --------
__device__ __forceinline__ ull ffma2(ull a, ull b, ull c) {
    ull d;
    asm("fma.rn.f32x2 %0, %1, %2, %3;" : "=l"(d) : "l"(a), "l"(b), "l"(c));
    return d;
}
__device__ __forceinline__ ull fmul2(ull a, ull b) {
    ull d;
    asm("mul.rn.f32x2 %0, %1, %2;" : "=l"(d) : "l"(a), "l"(b));
    return d;
}
__device__ __forceinline__ ull pk2(float x, float y) {
    ull r;
    asm("mov.b64 %0, {%1, %2};" : "=l"(r)
        : "r"(__float_as_uint(x)), "r"(__float_as_uint(y)));
    return r;
}
__device__ __forceinline__ float2 upk2(ull a) {
    unsigned lo, hi;
    asm("mov.b64 {%0, %1}, %2;" : "=r"(lo), "=r"(hi) : "l"(a));
    return make_float2(__uint_as_float(lo), __uint_as_float(hi));
}
__device__ __forceinline__ float ex2(float x) {
    float y;
    asm("ex2.approx.ftz.f32 %0, %1;" : "=f"(y) : "f"(x));
    return y;
}

// ============================================================================
// Kernel 1: fused QKV projection, f32x2-packed. 32 rows/block, grid (256, 3).
// ============================================================================
__global__ __launch_bounds__(256) void qkv_kernel(
    const float* __restrict__ X,
    const float* __restrict__ Wq,
    const float* __restrict__ Wk,
    const float* __restrict__ Wv)
{
    __shared__ float Xs[32][128];
    int which = blockIdx.y;
    const float* W = (which == 0) ? Wq : ((which == 1) ? Wk : Wv);
    float* out = (which == 0) ? g_Q : ((which == 1) ? g_K : g_V);
    float scale = (which == 0) ? (0.08838834764831845f * 1.4426950408889634f) : 1.0f;

    int row0 = blockIdx.x * 32;
    const float4* X4 = (const float4*)(X + row0 * 128);
    float4* Xs4 = (float4*)&Xs[0][0];
#pragma unroll
    for (int i = 0; i < 4; i++)
        Xs4[threadIdx.x + i * 256] = X4[threadIdx.x + i * 256];
    __syncthreads();

    int c4 = threadIdx.x & 31;
    int rg = threadIdx.x >> 5;

    ull acc01[4], acc23[4];
#pragma unroll
    for (int i = 0; i < 4; i++) { acc01[i] = 0ull; acc23[i] = 0ull; }

    const longlong2* WL = (const longlong2*)W;
    for (int d0 = 0; d0 < 128; d0 += 4) {
        longlong2 w0 = WL[(d0 + 0) * 32 + c4];
        longlong2 w1 = WL[(d0 + 1) * 32 + c4];
        longlong2 w2 = WL[(d0 + 2) * 32 + c4];
        longlong2 w3 = WL[(d0 + 3) * 32 + c4];
#pragma unroll
        for (int i = 0; i < 4; i++) {
            float4 a = *(const float4*)&Xs[rg * 4 + i][d0];
            ull ax = pk2(a.x, a.x), ay = pk2(a.y, a.y);
            ull az = pk2(a.z, a.z), aw = pk2(a.w, a.w);
            acc01[i] = ffma2(ax, (ull)w0.x, acc01[i]);
            acc23[i] = ffma2(ax, (ull)w0.y, acc23[i]);
            acc01[i] = ffma2(ay, (ull)w1.x, acc01[i]);
            acc23[i] = ffma2(ay, (ull)w1.y, acc23[i]);
            acc01[i] = ffma2(az, (ull)w2.x, acc01[i]);
            acc23[i] = ffma2(az, (ull)w2.y, acc23[i]);
            acc01[i] = ffma2(aw, (ull)w3.x, acc01[i]);
            acc23[i] = ffma2(aw, (ull)w3.y, acc23[i]);
        }
    }

    int col = c4 * 4;
    int h = col >> 4;
    int j = col & 15;
#pragma unroll
    for (int i = 0; i < 4; i++) {
        int row = row0 + rg * 4 + i;
        int b = row >> 11;
        int s = row & 2047;
        float2 lo = upk2(acc01[i]), hi = upk2(acc23[i]);
        float4 v = make_float4(lo.x * scale, lo.y * scale, hi.x * scale, hi.y * scale);
        *(float4*)&out[(((b * 8 + h) * NS + s) * 16) + j] = v;
    }
}

// ============================================================================
// Kernel 2a: transpose lin_w
// ============================================================================
__global__ void prep_kernel(const float* __restrict__ lw) {
    int t = blockIdx.x * 256 + threadIdx.x;
    if (t < 128 * 128) {
        int d = t >> 7, c = t & 127;
        g_LWT[t] = lw[c * 128 + d];
    }
}

// ============================================================================
// Kernel 2b: deterministic key compaction (one warp per batch).
// ============================================================================
__global__ void compact_kernel(const int* __restrict__ mask) {
    int b = blockIdx.x;
    int lane = threadIdx.x;
    const int* m = mask + b * NS;
    int base = 0;
    for (int k0 = 0; k0 < NS; k0 += 32) {
        int v = (m[k0 + lane] != 0);
        unsigned bal = __ballot_sync(0xffffffffu, v);
        int pos = base + __popc(bal & ((1u << lane) - 1u));
        if (v) g_list[b][pos] = k0 + lane;
        base += __popc(bal);
    }
    if (base == 0) {
        for (int i = lane; i < NS; i += 32) g_list[b][i] = i;
        base = NS;
    }
    int padded = (base + 15) & ~15;
    for (int i = base + lane; i < padded; i += 32) g_list[b][i] = 0;
    if (lane == 0) g_cnt[b] = base;
}

// ============================================================================
// Kernel 3: flash attention over COMPACTED keys, SPLIT-K x4, 2 QUERIES/THREAD.
// grid (8, 32, 4): x = query supertile (256 rows), y = (b,h), z = key split.
// One K/V smem read now feeds two queries' FMA work (halves LDS pressure).
// ============================================================================
__global__ __launch_bounds__(128) void attn_kernel() {
    __shared__ float4 KV[128];   // [0..63] K tile (16 keys x 16f), [64..127] V tile
    __shared__ int lst[512];     // this split's compacted key indices

    int bh = blockIdx.y;
    int b = bh >> 3;
    int sp = blockIdx.z;
    int tid = threadIdx.x;

    int cnt = g_cnt[b];
    int ntiles = (cnt + 15) >> 4;
    int tps = (ntiles + NSPLIT - 1) >> 2;
    int t0 = sp * tps;
    int t1 = min(ntiles, t0 + tps);

    int ra = blockIdx.x * 256 + tid;          // query a
    int pa = (sp * NBH + bh) * NS + ra;       // partial index a
    int pb = pa + 128;                        // partial index b (query ra+128)

    if (t0 >= t1) {                           // empty split (block-uniform)
        float4 z = make_float4(0.f, 0.f, 0.f, 0.f);
        g_Pml[pa] = make_float2(-1e30f, 0.f);
        g_Pml[pb] = make_float2(-1e30f, 0.f);
        float4* Pa = &g_Po[(size_t)pa * 4];
        float4* Pb = &g_Po[(size_t)pb * 4];
#pragma unroll
        for (int i = 0; i < 4; i++) { Pa[i] = z; Pb[i] = z; }
        return;
    }

    for (int i = tid; i < (t1 - t0) * 16; i += 128)
        lst[i] = g_list[b][t0 * 16 + i];

    ull qa[8], qb[8];
    {
        const longlong2* Q2a = (const longlong2*)(g_Q + ((size_t)bh * NS + ra) * 16);
        const longlong2* Q2b = Q2a + 128 * 4;    // query ra+128
#pragma unroll
        for (int i = 0; i < 4; i++) {
            longlong2 ta = Q2a[i], tb = Q2b[i];
            qa[2 * i] = (ull)ta.x; qa[2 * i + 1] = (ull)ta.y;
            qb[2 * i] = (ull)tb.x; qb[2 * i + 1] = (ull)tb.y;
        }
    }
    __syncthreads();

    float ma = -1e30f, la = 0.f, mb = -1e30f, lb = 0.f;
    ull oa[8], ob[8];
#pragma unroll
    for (int i = 0; i < 8; i++) { oa[i] = 0ull; ob[i] = 0ull; }

    const float4* Kb4 = (const float4*)(g_K + (size_t)bh * NS * 16);
    const float4* Vb4 = (const float4*)(g_V + (size_t)bh * NS * 16);

    for (int t = t0; t < t1; t++) {
        {
            int i = tid & 63;
            int row = i >> 2, part = i & 3;
            int kidx = lst[(t - t0) * 16 + row];
            const float4* src = (tid < 64) ? (Kb4 + (size_t)kidx * 4 + part)
                                           : (Vb4 + (size_t)kidx * 4 + part);
            KV[(tid & 64) + row * 4 + part] = *src;
        }
        __syncthreads();

        float sva[16], svb[16];
#pragma unroll
        for (int j = 0; j < 16; j++) {
            const longlong2* kj = (const longlong2*)&KV[j * 4];
            longlong2 k0 = kj[0], k1 = kj[1];
            ull a0 = fmul2(qa[0], (ull)k0.x);
            ull b0 = fmul2(qb[0], (ull)k0.x);
            ull a1 = fmul2(qa[1], (ull)k0.y);
            ull b1 = fmul2(qb[1], (ull)k0.y);
            a0 = ffma2(qa[2], (ull)k1.x, a0);
            b0 = ffma2(qb[2], (ull)k1.x, b0);
            a1 = ffma2(qa[3], (ull)k1.y, a1);
            b1 = ffma2(qb[3], (ull)k1.y, b1);
            longlong2 k2 = kj[2], k3 = kj[3];
            a0 = ffma2(qa[4], (ull)k2.x, a0);
            b0 = ffma2(qb[4], (ull)k2.x, b0);
            a1 = ffma2(qa[5], (ull)k2.y, a1);
            b1 = ffma2(qb[5], (ull)k2.y, b1);
            a0 = ffma2(qa[6], (ull)k3.x, a0);
            b0 = ffma2(qb[6], (ull)k3.x, b0);
            a1 = ffma2(qa[7], (ull)k3.y, a1);
            b1 = ffma2(qb[7], (ull)k3.y, b1);
            float2 ua = upk2(a0), va = upk2(a1);
            float2 ub = upk2(b0), vb = upk2(b1);
            sva[j] = (ua.x + ua.y) + (va.x + va.y);
            svb[j] = (ub.x + ub.y) + (vb.x + vb.y);
        }

        // only the globally-last tile carries padding keys (uniform branch)
        if (t == ntiles - 1) {
            int lim = cnt - (t << 4);
#pragma unroll
            for (int j = 0; j < 16; j++)
                if (j >= lim) { sva[j] = -1e30f; svb[j] = -1e30f; }
        }

        float tma = sva[0], tmb = svb[0];
#pragma unroll
        for (int j = 1; j < 16; j++) {
            tma = fmaxf(tma, sva[j]);
            tmb = fmaxf(tmb, svb[j]);
        }
        if (tma > ma) {
            float corr = ex2(ma - tma);    // 0 on first tile
            la *= corr;
            ull c2 = pk2(corr, corr);
#pragma unroll
            for (int i = 0; i < 8; i++) oa[i] = fmul2(oa[i], c2);
            ma = tma;
        }
        if (tmb > mb) {
            float corr = ex2(mb - tmb);
            lb *= corr;
            ull c2 = pk2(corr, corr);
#pragma unroll
            for (int i = 0; i < 8; i++) ob[i] = fmul2(ob[i], c2);
            mb = tmb;
        }

#pragma unroll
        for (int j = 0; j < 16; j++) {
            float pA = ex2(sva[j] - ma);
            float pB = ex2(svb[j] - mb);
            la += pA;
            lb += pB;
            ull p2a = pk2(pA, pA);
            ull p2b = pk2(pB, pB);
            const longlong2* vj = (const longlong2*)&KV[64 + j * 4];
            longlong2 v0 = vj[0], v1 = vj[1];
            oa[0] = ffma2(p2a, (ull)v0.x, oa[0]);
            ob[0] = ffma2(p2b, (ull)v0.x, ob[0]);
            oa[1] = ffma2(p2a, (ull)v0.y, oa[1]);
            ob[1] = ffma2(p2b, (ull)v0.y, ob[1]);
            oa[2] = ffma2(p2a, (ull)v1.x, oa[2]);
            ob[2] = ffma2(p2b, (ull)v1.x, ob[2]);
            oa[3] = ffma2(p2a, (ull)v1.y, oa[3]);
            ob[3] = ffma2(p2b, (ull)v1.y, ob[3]);
            longlong2 v2 = vj[2], v3 = vj[3];
            oa[4] = ffma2(p2a, (ull)v2.x, oa[4]);
            ob[4] = ffma2(p2b, (ull)v2.x, ob[4]);
            oa[5] = ffma2(p2a, (ull)v2.y, oa[5]);
            ob[5] = ffma2(p2b, (ull)v2.y, ob[5]);
            oa[6] = ffma2(p2a, (ull)v3.x, oa[6]);
            ob[6] = ffma2(p2b, (ull)v3.x, ob[6]);
            oa[7] = ffma2(p2a, (ull)v3.y, oa[7]);
            ob[7] = ffma2(p2b, (ull)v3.y, ob[7]);
        }
        __syncthreads();
    }

    g_Pml[pa] = make_float2(ma, la);
    g_Pml[pb] = make_float2(mb, lb);
    float4* Pa = &g_Po[(size_t)pa * 4];
    float4* Pb = &g_Po[(size_t)pb * 4];
#pragma unroll
    for (int i = 0; i < 4; i++) {
        float2 xa = upk2(oa[2 * i]), ya = upk2(oa[2 * i + 1]);
        float2 xb = upk2(ob[2 * i]), yb = upk2(ob[2 * i + 1]);
        Pa[i] = make_float4(xa.x, xa.y, ya.x, ya.y);
        Pb[i] = make_float4(xb.x, xb.y, yb.x, yb.y);
    }
}

// ============================================================================
// Kernel 3b: combine split-K partials -> g_O. One thread per query.
// ============================================================================
__global__ __launch_bounds__(256) void combine_kernel() {
    int q = blockIdx.x * 256 + threadIdx.x;

    float2 ml[NSPLIT];
    float M = -1e30f;
#pragma unroll
    for (int s = 0; s < NSPLIT; s++) {
        ml[s] = g_Pml[s * NQ + q];
        M = fmaxf(M, ml[s].x);
    }
    float l = 0.f;
    float4 o0 = make_float4(0, 0, 0, 0), o1 = o0, o2v = o0, o3 = o0;
#pragma unroll
    for (int s = 0; s < NSPLIT; s++) {
        float w = ex2(ml[s].x - M);
        l += ml[s].y * w;
        const float4* P = &g_Po[((size_t)s * NQ + q) * 4];
        float4 p0 = P[0], p1 = P[1], p2 = P[2], p3 = P[3];
        o0.x += p0.x * w; o0.y += p0.y * w; o0.z += p0.z * w; o0.w += p0.w * w;
        o1.x += p1.x * w; o1.y += p1.y * w; o1.z += p1.z * w; o1.w += p1.w * w;
        o2v.x += p2.x * w; o2v.y += p2.y * w; o2v.z += p2.z * w; o2v.w += p2.w * w;
        o3.x += p3.x * w; o3.y += p3.y * w; o3.z += p3.z * w; o3.w += p3.w * w;
    }
    float inv = 1.0f / l;
    float4* O = (float4*)(g_O + (size_t)q * 16);
    O[0] = make_float4(o0.x * inv, o0.y * inv, o0.z * inv, o0.w * inv);
    O[1] = make_float4(o1.x * inv, o1.y * inv, o1.z * inv, o1.w * inv);
    O[2] = make_float4(o2v.x * inv, o2v.y * inv, o2v.z * inv, o2v.w * inv);
    O[3] = make_float4(o3.x * inv, o3.y * inv, o3.z * inv, o3.w * inv);
}

// ============================================================================
// Kernel 4: output projection, f32x2-packed. 32 rows/block, grid 256.
// ============================================================================
__global__ __launch_bounds__(256) void proj_kernel(
    const float* __restrict__ bias, float* __restrict__ out)
{
    __shared__ float Xs[32][128];
    int row0 = blockIdx.x * 32;

#pragma unroll
    for (int ii = 0; ii < 4; ii++) {
        int i = threadIdx.x + ii * 256;
        int rr = i >> 5, cc4 = i & 31;
        int row = row0 + rr;
        int b = row >> 11, s = row & 2047;
        int col = cc4 * 4;
        int hh = c_ord[col >> 4];
        int j = col & 15;
        *(float4*)&Xs[rr][col] =
            *(const float4*)&g_O[(((b * 8 + hh) * NS + s) * 16) + j];
    }
    __syncthreads();

    int c4 = threadIdx.x & 31;
    int rg = threadIdx.x >> 5;

    float4 bb = ((const float4*)bias)[c4];
    ull acc01[4], acc23[4];
#pragma unroll
    for (int i = 0; i < 4; i++) {
        acc01[i] = pk2(bb.x, bb.y);
        acc23[i] = pk2(bb.z, bb.w);
    }

    const longlong2* WL = (const longlong2*)g_LWT;
    for (int d0 = 0; d0 < 128; d0 += 4) {
        longlong2 w0 = WL[(d0 + 0) * 32 + c4];
        longlong2 w1 = WL[(d0 + 1) * 32 + c4];
        longlong2 w2 = WL[(d0 + 2) * 32 + c4];
        longlong2 w3 = WL[(d0 + 3) * 32 + c4];
#pragma unroll
        for (int i = 0; i < 4; i++) {
            float4 a = *(const float4*)&Xs[rg * 4 + i][d0];
            ull ax = pk2(a.x, a.x), ay = pk2(a.y, a.y);
            ull az = pk2(a.z, a.z), aw = pk2(a.w, a.w);
            acc01[i] = ffma2(ax, (ull)w0.x, acc01[i]);
            acc23[i] = ffma2(ax, (ull)w0.y, acc23[i]);
            acc01[i] = ffma2(ay, (ull)w1.x, acc01[i]);
            acc23[i] = ffma2(ay, (ull)w1.y, acc23[i]);
            acc01[i] = ffma2(az, (ull)w2.x, acc01[i]);
            acc23[i] = ffma2(az, (ull)w2.y, acc23[i]);
            acc01[i] = ffma2(aw, (ull)w3.x, acc01[i]);
            acc23[i] = ffma2(aw, (ull)w3.y, acc23[i]);
        }
    }

#pragma unroll
    for (int i = 0; i < 4; i++) {
        int row = row0 + rg * 4 + i;
        float2 lo = upk2(acc01[i]), hi = upk2(acc23[i]);
        ((float4*)out)[row * 32 + c4] = make_float4(lo.x, lo.y, hi.x, hi.y);
    }
}

// ============================================================================
extern "C" void kernel_launch(void* const* d_in, const int* in_sizes, int n_in,
                              void* d_out, int out_size) {
    const float* X    = (const float*)d_in[0];
    const int*   mask = (const int*)d_in[1];
    const float* Wq   = (const float*)d_in[2];
    const float* Wk   = (const float*)d_in[3];
    const float* Wv   = (const float*)d_in[4];
    const float* lw   = (const float*)d_in[5];
    const float* lb   = (const float*)d_in[6];
    float* out = (float*)d_out;

    qkv_kernel<<<dim3(256, 3), 256>>>(X, Wq, Wk, Wv);
    prep_kernel<<<64, 256>>>(lw);
    compact_kernel<<<NB, 32>>>(mask);
    attn_kernel<<<dim3(8, 32, NSPLIT), 128>>>();
    combine_kernel<<<NQ / 256, 256>>>();
    proj_kernel<<<256, 256>>>(lb, out);
}

// round 14
// speedup vs baseline: 2.1639x; 1.0494x over previous
#include <cuda_runtime.h>

typedef unsigned long long ull;

#define NS   2048
#define NB   4
#define NH   8
#define NBH  32        // NB*NH
#define NROWS 8192     // NB*NS
#define NSPLIT 4
#define NQ   (NBH * NS)   // 65536 total queries

// -------- scratch (static __device__ arrays; no allocation allowed) --------
__device__ float g_Q[NBH * NS * 16];   // [b,h,s,j], Q pre-scaled by log2(e)/sqrt(128)
__device__ float g_K[NBH * NS * 16];
__device__ float g_V[NBH * NS * 16];
__device__ float g_O[NBH * NS * 16];   // attention output per head
__device__ float g_LWT[128 * 128];     // lin_w transposed
__device__ int   g_cnt[NB];            // compacted (unmasked) key count per batch
__device__ int   g_list[NB][NS];       // compacted key indices per batch
__device__ float2 g_Pml[NSPLIT * NQ];      // per-split (m, l)
__device__ float4 g_Po[NSPLIT * NQ * 4];   // per-split unnormalized o (16 floats)

// buggy concat order kept faithful to the reference
__constant__ int c_ord[8] = {0, 1, 1, 2, 3, 4, 5, 6};

// -------- packed f32x2 + fast exp2 helpers --------
__device__ __forceinline__ ull ffma2(ull a, ull b, ull c) {
    ull d;
    asm("fma.rn.f32x2 %0, %1, %2, %3;" : "=l"(d) : "l"(a), "l"(b), "l"(c));
    return d;
}
__device__ __forceinline__ ull fmul2(ull a, ull b) {
    ull d;
    asm("mul.rn.f32x2 %0, %1, %2;" : "=l"(d) : "l"(a), "l"(b));
    return d;
}
__device__ __forceinline__ ull pk2(float x, float y) {
    ull r;
    asm("mov.b64 %0, {%1, %2};" : "=l"(r)
        : "r"(__float_as_uint(x)), "r"(__float_as_uint(y)));
    return r;
}
__device__ __forceinline__ float2 upk2(ull a) {
    unsigned lo, hi;
    asm("mov.b64 {%0, %1}, %2;" : "=r"(lo), "=r"(hi) : "l"(a));
    return make_float2(__uint_as_float(lo), __uint_as_float(hi));
}
__device__ __forceinline__ float ex2(float x) {
    float y;
    asm("ex2.approx.ftz.f32 %0, %1;" : "=f"(y) : "f"(x));
    return y;
}

// -------- attn inner-loop helpers --------
// QK score for one key j against both queries (16-dim dot each).
__device__ __forceinline__ void qk_score(const ull* qa, const ull* qb,
                                         const float4* kv, int j,
                                         float& sa, float& sb) {
    const longlong2* kj = (const longlong2*)&kv[j * 4];
    longlong2 k0 = kj[0], k1 = kj[1];
    ull a0 = fmul2(qa[0], (ull)k0.x);
    ull b0 = fmul2(qb[0], (ull)k0.x);
    ull a1 = fmul2(qa[1], (ull)k0.y);
    ull b1 = fmul2(qb[1], (ull)k0.y);
    a0 = ffma2(qa[2], (ull)k1.x, a0);
    b0 = ffma2(qb[2], (ull)k1.x, b0);
    a1 = ffma2(qa[3], (ull)k1.y, a1);
    b1 = ffma2(qb[3], (ull)k1.y, b1);
    longlong2 k2 = kj[2], k3 = kj[3];
    a0 = ffma2(qa[4], (ull)k2.x, a0);
    b0 = ffma2(qb[4], (ull)k2.x, b0);
    a1 = ffma2(qa[5], (ull)k2.y, a1);
    b1 = ffma2(qb[5], (ull)k2.y, b1);
    a0 = ffma2(qa[6], (ull)k3.x, a0);
    b0 = ffma2(qb[6], (ull)k3.x, b0);
    a1 = ffma2(qa[7], (ull)k3.y, a1);
    b1 = ffma2(qb[7], (ull)k3.y, b1);
    float2 ua = upk2(a0), va = upk2(a1);
    float2 ub = upk2(b0), vb = upk2(b1);
    sa = (ua.x + ua.y) + (va.x + va.y);
    sb = (ub.x + ub.y) + (vb.x + vb.y);
}

// o += p * V[j], both queries
__device__ __forceinline__ void pv_acc(float pA, float pB,
                                       const float4* kv, int j,
                                       ull* oa, ull* ob) {
    ull p2a = pk2(pA, pA), p2b = pk2(pB, pB);
    const longlong2* vj = (const longlong2*)&kv[128 + j * 4];
    longlong2 v0 = vj[0], v1 = vj[1];
    oa[0] = ffma2(p2a, (ull)v0.x, oa[0]);
    ob[0] = ffma2(p2b, (ull)v0.x, ob[0]);
    oa[1] = ffma2(p2a, (ull)v0.y, oa[1]);
    ob[1] = ffma2(p2b, (ull)v0.y, ob[1]);
    longlong2 v2 = vj[2], v3 = vj[3];
    oa[2] = ffma2(p2a, (ull)v1.x, oa[2]);
    ob[2] = ffma2(p2b, (ull)v1.x, ob[2]);
    oa[3] = ffma2(p2a, (ull)v1.y, oa[3]);
    ob[3] = ffma2(p2b, (ull)v1.y, ob[3]);
    oa[4] = ffma2(p2a, (ull)v2.x, oa[4]);
    ob[4] = ffma2(p2b, (ull)v2.x, ob[4]);
    oa[5] = ffma2(p2a, (ull)v2.y, oa[5]);
    ob[5] = ffma2(p2b, (ull)v2.y, ob[5]);
    oa[6] = ffma2(p2a, (ull)v3.x, oa[6]);
    ob[6] = ffma2(p2b, (ull)v3.x, ob[6]);
    oa[7] = ffma2(p2a, (ull)v3.y, oa[7]);
    ob[7] = ffma2(p2b, (ull)v3.y, ob[7]);
}

__device__ __forceinline__ void rescale(float tm, float& m, float& l, ull* o) {
    if (tm > m) {
        float corr = ex2(m - tm);      // 0 on first chunk
        l *= corr;
        ull c2 = pk2(corr, corr);
#pragma unroll
        for (int i = 0; i < 8; i++) o[i] = fmul2(o[i], c2);
        m = tm;
    }
}

// ============================================================================
// Kernel 1: fused QKV projection, f32x2-packed. 32 rows/block, grid (256, 3).
// ============================================================================
__global__ __launch_bounds__(256) void qkv_kernel(
    const float* __restrict__ X,
    const float* __restrict__ Wq,
    const float* __restrict__ Wk,
    const float* __restrict__ Wv)
{
    __shared__ float Xs[32][128];
    int which = blockIdx.y;
    const float* W = (which == 0) ? Wq : ((which == 1) ? Wk : Wv);
    float* out = (which == 0) ? g_Q : ((which == 1) ? g_K : g_V);
    float scale = (which == 0) ? (0.08838834764831845f * 1.4426950408889634f) : 1.0f;

    int row0 = blockIdx.x * 32;
    const float4* X4 = (const float4*)(X + row0 * 128);
    float4* Xs4 = (float4*)&Xs[0][0];
#pragma unroll
    for (int i = 0; i < 4; i++)
        Xs4[threadIdx.x + i * 256] = X4[threadIdx.x + i * 256];
    __syncthreads();

    int c4 = threadIdx.x & 31;
    int rg = threadIdx.x >> 5;

    ull acc01[4], acc23[4];
#pragma unroll
    for (int i = 0; i < 4; i++) { acc01[i] = 0ull; acc23[i] = 0ull; }

    const longlong2* WL = (const longlong2*)W;
    for (int d0 = 0; d0 < 128; d0 += 4) {
        longlong2 w0 = WL[(d0 + 0) * 32 + c4];
        longlong2 w1 = WL[(d0 + 1) * 32 + c4];
        longlong2 w2 = WL[(d0 + 2) * 32 + c4];
        longlong2 w3 = WL[(d0 + 3) * 32 + c4];
#pragma unroll
        for (int i = 0; i < 4; i++) {
            float4 a = *(const float4*)&Xs[rg * 4 + i][d0];
            ull ax = pk2(a.x, a.x), ay = pk2(a.y, a.y);
            ull az = pk2(a.z, a.z), aw = pk2(a.w, a.w);
            acc01[i] = ffma2(ax, (ull)w0.x, acc01[i]);
            acc23[i] = ffma2(ax, (ull)w0.y, acc23[i]);
            acc01[i] = ffma2(ay, (ull)w1.x, acc01[i]);
            acc23[i] = ffma2(ay, (ull)w1.y, acc23[i]);
            acc01[i] = ffma2(az, (ull)w2.x, acc01[i]);
            acc23[i] = ffma2(az, (ull)w2.y, acc23[i]);
            acc01[i] = ffma2(aw, (ull)w3.x, acc01[i]);
            acc23[i] = ffma2(aw, (ull)w3.y, acc23[i]);
        }
    }

    int col = c4 * 4;
    int h = col >> 4;
    int j = col & 15;
#pragma unroll
    for (int i = 0; i < 4; i++) {
        int row = row0 + rg * 4 + i;
        int b = row >> 11;
        int s = row & 2047;
        float2 lo = upk2(acc01[i]), hi = upk2(acc23[i]);
        float4 v = make_float4(lo.x * scale, lo.y * scale, hi.x * scale, hi.y * scale);
        *(float4*)&out[(((b * 8 + h) * NS + s) * 16) + j] = v;
    }
}

// ============================================================================
// Kernel 2: merged lin_w transpose + key compaction (saves a launch).
// Blocks 0..63: transpose. Blocks 64..67: compact batch (blk-64), warp 0 only.
// ============================================================================
__global__ void prep_compact_kernel(const float* __restrict__ lw,
                                    const int* __restrict__ mask) {
    if (blockIdx.x < 64) {
        int t = blockIdx.x * 256 + threadIdx.x;
        int d = t >> 7, c = t & 127;
        g_LWT[t] = lw[c * 128 + d];
        return;
    }
    if (threadIdx.x >= 32) return;
    int b = blockIdx.x - 64;
    int lane = threadIdx.x;
    const int* m = mask + b * NS;
    int base = 0;
    for (int k0 = 0; k0 < NS; k0 += 32) {
        int v = (m[k0 + lane] != 0);
        unsigned bal = __ballot_sync(0xffffffffu, v);
        int pos = base + __popc(bal & ((1u << lane) - 1u));
        if (v) g_list[b][pos] = k0 + lane;
        base += __popc(bal);
    }
    if (base == 0) {
        for (int i = lane; i < NS; i += 32) g_list[b][i] = i;
        base = NS;
    }
    int padded = (base + 31) & ~31;              // pad to tile of 32
    for (int i = base + lane; i < padded; i += 32) g_list[b][i] = 0;
    if (lane == 0) g_cnt[b] = base;
}

// ============================================================================
// Kernel 3: flash attention, compacted keys, split-K x4, 2 queries/thread.
// Chunked 2-pass (8-key chunks) -> no big score arrays -> <=128 regs
// -> 4 blocks/SM. Key tile = 32 in smem (one sync pair per 32 keys).
// grid (8, 32, 4).
// ============================================================================
__global__ __launch_bounds__(128, 4) void attn_kernel() {
    __shared__ float4 KV[256];   // [0..127] K (32 keys x 16f), [128..255] V
    __shared__ int lst[512];     // this split's compacted key indices

    int bh = blockIdx.y;
    int b = bh >> 3;
    int sp = blockIdx.z;
    int tid = threadIdx.x;

    int cnt = g_cnt[b];
    int ntiles = (cnt + 31) >> 5;
    int tps = (ntiles + NSPLIT - 1) >> 2;
    int t0 = sp * tps;
    int t1 = min(ntiles, t0 + tps);

    int ra = blockIdx.x * 256 + tid;          // query a
    int pa = (sp * NBH + bh) * NS + ra;
    int pb = pa + 128;                        // query a+128

    if (t0 >= t1) {                           // empty split (block-uniform)
        float4 z = make_float4(0.f, 0.f, 0.f, 0.f);
        g_Pml[pa] = make_float2(-1e30f, 0.f);
        g_Pml[pb] = make_float2(-1e30f, 0.f);
        float4* Pa = &g_Po[(size_t)pa * 4];
        float4* Pb = &g_Po[(size_t)pb * 4];
#pragma unroll
        for (int i = 0; i < 4; i++) { Pa[i] = z; Pb[i] = z; }
        return;
    }

    for (int i = tid; i < (t1 - t0) * 32; i += 128)
        lst[i] = g_list[b][t0 * 32 + i];

    ull qa[8], qb[8];
    {
        const longlong2* Q2a = (const longlong2*)(g_Q + ((size_t)bh * NS + ra) * 16);
        const longlong2* Q2b = Q2a + 128 * 4;
#pragma unroll
        for (int i = 0; i < 4; i++) {
            longlong2 ta = Q2a[i], tb = Q2b[i];
            qa[2 * i] = (ull)ta.x; qa[2 * i + 1] = (ull)ta.y;
            qb[2 * i] = (ull)tb.x; qb[2 * i + 1] = (ull)tb.y;
        }
    }
    __syncthreads();

    float ma = -1e30f, la = 0.f, mb = -1e30f, lb = 0.f;
    ull oa[8], ob[8];
#pragma unroll
    for (int i = 0; i < 8; i++) { oa[i] = 0ull; ob[i] = 0ull; }

    const float4* Kb4 = (const float4*)(g_K + (size_t)bh * NS * 16);
    const float4* Vb4 = (const float4*)(g_V + (size_t)bh * NS * 16);

    int lrow = tid >> 2, lpart = tid & 3;     // tile-load role

    for (int t = t0; t < t1; t++) {
        {
            int kidx = lst[(t - t0) * 32 + lrow];
            KV[lrow * 4 + lpart]       = Kb4[(size_t)kidx * 4 + lpart];
            KV[128 + lrow * 4 + lpart] = Vb4[(size_t)kidx * 4 + lpart];
        }
        __syncthreads();

        int jlim = min(32, cnt - (t << 5));   // partial only for global last tile
        if (jlim == 32) {
#pragma unroll
            for (int c = 0; c < 4; c++) {     // 4 chunks of 8 keys
                float sva[8], svb[8];
#pragma unroll
                for (int j = 0; j < 8; j++)
                    qk_score(qa, qb, KV, c * 8 + j, sva[j], svb[j]);

                float tma = sva[0], tmb = svb[0];
#pragma unroll
                for (int j = 1; j < 8; j++) {
                    tma = fmaxf(tma, sva[j]);
                    tmb = fmaxf(tmb, svb[j]);
                }
                rescale(tma, ma, la, oa);
                rescale(tmb, mb, lb, ob);

#pragma unroll
                for (int j = 0; j < 8; j++) {
                    float pA = ex2(sva[j] - ma);
                    float pB = ex2(svb[j] - mb);
                    la += pA;
                    lb += pB;
                    pv_acc(pA, pB, KV, c * 8 + j, oa, ob);
                }
            }
        } else {
            for (int j = 0; j < jlim; j++) {  // ragged tail, once per block max
                float sa, sb;
                qk_score(qa, qb, KV, j, sa, sb);
                rescale(sa, ma, la, oa);
                rescale(sb, mb, lb, ob);
                float pA = ex2(sa - ma);
                float pB = ex2(sb - mb);
                la += pA;
                lb += pB;
                pv_acc(pA, pB, KV, j, oa, ob);
            }
        }
        __syncthreads();
    }

    g_Pml[pa] = make_float2(ma, la);
    g_Pml[pb] = make_float2(mb, lb);
    float4* Pa = &g_Po[(size_t)pa * 4];
    float4* Pb = &g_Po[(size_t)pb * 4];
#pragma unroll
    for (int i = 0; i < 4; i++) {
        float2 xa = upk2(oa[2 * i]), ya = upk2(oa[2 * i + 1]);
        float2 xb = upk2(ob[2 * i]), yb = upk2(ob[2 * i + 1]);
        Pa[i] = make_float4(xa.x, xa.y, ya.x, ya.y);
        Pb[i] = make_float4(xb.x, xb.y, yb.x, yb.y);
    }
}

// ============================================================================
// Kernel 3b: combine split-K partials -> g_O. One thread per query.
// ============================================================================
__global__ __launch_bounds__(256) void combine_kernel() {
    int q = blockIdx.x * 256 + threadIdx.x;

    float2 ml[NSPLIT];
    float M = -1e30f;
#pragma unroll
    for (int s = 0; s < NSPLIT; s++) {
        ml[s] = g_Pml[s * NQ + q];
        M = fmaxf(M, ml[s].x);
    }
    float l = 0.f;
    float4 o0 = make_float4(0, 0, 0, 0), o1 = o0, o2v = o0, o3 = o0;
#pragma unroll
    for (int s = 0; s < NSPLIT; s++) {
        float w = ex2(ml[s].x - M);
        l += ml[s].y * w;
        const float4* P = &g_Po[((size_t)s * NQ + q) * 4];
        float4 p0 = P[0], p1 = P[1], p2 = P[2], p3 = P[3];
        o0.x += p0.x * w; o0.y += p0.y * w; o0.z += p0.z * w; o0.w += p0.w * w;
        o1.x += p1.x * w; o1.y += p1.y * w; o1.z += p1.z * w; o1.w += p1.w * w;
        o2v.x += p2.x * w; o2v.y += p2.y * w; o2v.z += p2.z * w; o2v.w += p2.w * w;
        o3.x += p3.x * w; o3.y += p3.y * w; o3.z += p3.z * w; o3.w += p3.w * w;
    }
    float inv = 1.0f / l;
    float4* O = (float4*)(g_O + (size_t)q * 16);
    O[0] = make_float4(o0.x * inv, o0.y * inv, o0.z * inv, o0.w * inv);
    O[1] = make_float4(o1.x * inv, o1.y * inv, o1.z * inv, o1.w * inv);
    O[2] = make_float4(o2v.x * inv, o2v.y * inv, o2v.z * inv, o2v.w * inv);
    O[3] = make_float4(o3.x * inv, o3.y * inv, o3.z * inv, o3.w * inv);
}

// ============================================================================
// Kernel 4: output projection, f32x2-packed. 32 rows/block, grid 256.
// ============================================================================
__global__ __launch_bounds__(256) void proj_kernel(
    const float* __restrict__ bias, float* __restrict__ out)
{
    __shared__ float Xs[32][128];
    int row0 = blockIdx.x * 32;

#pragma unroll
    for (int ii = 0; ii < 4; ii++) {
        int i = threadIdx.x + ii * 256;
        int rr = i >> 5, cc4 = i & 31;
        int row = row0 + rr;
        int b = row >> 11, s = row & 2047;
        int col = cc4 * 4;
        int hh = c_ord[col >> 4];
        int j = col & 15;
        *(float4*)&Xs[rr][col] =
            *(const float4*)&g_O[(((b * 8 + hh) * NS + s) * 16) + j];
    }
    __syncthreads();

    int c4 = threadIdx.x & 31;
    int rg = threadIdx.x >> 5;

    float4 bb = ((const float4*)bias)[c4];
    ull acc01[4], acc23[4];
#pragma unroll
    for (int i = 0; i < 4; i++) {
        acc01[i] = pk2(bb.x, bb.y);
        acc23[i] = pk2(bb.z, bb.w);
    }

    const longlong2* WL = (const longlong2*)g_LWT;
    for (int d0 = 0; d0 < 128; d0 += 4) {
        longlong2 w0 = WL[(d0 + 0) * 32 + c4];
        longlong2 w1 = WL[(d0 + 1) * 32 + c4];
        longlong2 w2 = WL[(d0 + 2) * 32 + c4];
        longlong2 w3 = WL[(d0 + 3) * 32 + c4];
#pragma unroll
        for (int i = 0; i < 4; i++) {
            float4 a = *(const float4*)&Xs[rg * 4 + i][d0];
            ull ax = pk2(a.x, a.x), ay = pk2(a.y, a.y);
            ull az = pk2(a.z, a.z), aw = pk2(a.w, a.w);
            acc01[i] = ffma2(ax, (ull)w0.x, acc01[i]);
            acc23[i] = ffma2(ax, (ull)w0.y, acc23[i]);
            acc01[i] = ffma2(ay, (ull)w1.x, acc01[i]);
            acc23[i] = ffma2(ay, (ull)w1.y, acc23[i]);
            acc01[i] = ffma2(az, (ull)w2.x, acc01[i]);
            acc23[i] = ffma2(az, (ull)w2.y, acc23[i]);
            acc01[i] = ffma2(aw, (ull)w3.x, acc01[i]);
            acc23[i] = ffma2(aw, (ull)w3.y, acc23[i]);
        }
    }

#pragma unroll
    for (int i = 0; i < 4; i++) {
        int row = row0 + rg * 4 + i;
        float2 lo = upk2(acc01[i]), hi = upk2(acc23[i]);
        ((float4*)out)[row * 32 + c4] = make_float4(lo.x, lo.y, hi.x, hi.y);
    }
}

// ============================================================================
extern "C" void kernel_launch(void* const* d_in, const int* in_sizes, int n_in,
                              void* d_out, int out_size) {
    const float* X    = (const float*)d_in[0];
    const int*   mask = (const int*)d_in[1];
    const float* Wq   = (const float*)d_in[2];
    const float* Wk   = (const float*)d_in[3];
    const float* Wv   = (const float*)d_in[4];
    const float* lw   = (const float*)d_in[5];
    const float* lb   = (const float*)d_in[6];
    float* out = (float*)d_out;

    qkv_kernel<<<dim3(256, 3), 256>>>(X, Wq, Wk, Wv);
    prep_compact_kernel<<<68, 256>>>(lw, mask);
    attn_kernel<<<dim3(8, 32, NSPLIT), 128>>>();
    combine_kernel<<<NQ / 256, 256>>>();
    proj_kernel<<<256, 256>>>(lb, out);
}

// round 16
// speedup vs baseline: 2.1866x; 1.0105x over previous
#include <cuda_runtime.h>

typedef unsigned long long ull;

#define NS   2048
#define NB   4
#define NH   8
#define NBH  32        // NB*NH
#define NROWS 8192     // NB*NS
#define NSPLIT 4
#define NQ   (NBH * NS)   // 65536 total queries

// -------- scratch (static __device__ arrays; no allocation allowed) --------
__device__ float g_Q[NBH * NS * 16];   // [b,h,s,j], Q pre-scaled by log2(e)/sqrt(128)
__device__ float g_K[NBH * NS * 16];
__device__ float g_V[NBH * NS * 16];
__device__ float g_O[NBH * NS * 16];   // attention output per head
__device__ float g_LWT[128 * 128];     // lin_w transposed
__device__ int   g_cnt[NB];            // compacted (unmasked) key count per batch
__device__ int   g_list[NB][NS];       // compacted key indices per batch
__device__ float2 g_Pml[NSPLIT * NQ];      // per-split (m, l)
__device__ float4 g_Po[NSPLIT * NQ * 4];   // per-split unnormalized o (16 floats)

// buggy concat order kept faithful to the reference
__constant__ int c_ord[8] = {0, 1, 1, 2, 3, 4, 5, 6};

// -------- packed f32x2 + fast exp2 helpers --------
__device__ __forceinline__ ull ffma2(ull a, ull b, ull c) {
    ull d;
    asm("fma.rn.f32x2 %0, %1, %2, %3;" : "=l"(d) : "l"(a), "l"(b), "l"(c));
    return d;
}
__device__ __forceinline__ ull fmul2(ull a, ull b) {
    ull d;
    asm("mul.rn.f32x2 %0, %1, %2;" : "=l"(d) : "l"(a), "l"(b));
    return d;
}
__device__ __forceinline__ ull pk2(float x, float y) {
    ull r;
    asm("mov.b64 %0, {%1, %2};" : "=l"(r)
        : "r"(__float_as_uint(x)), "r"(__float_as_uint(y)));
    return r;
}
__device__ __forceinline__ float2 upk2(ull a) {
    unsigned lo, hi;
    asm("mov.b64 {%0, %1}, %2;" : "=r"(lo), "=r"(hi) : "l"(a));
    return make_float2(__uint_as_float(lo), __uint_as_float(hi));
}
__device__ __forceinline__ float ex2(float x) {
    float y;
    asm("ex2.approx.ftz.f32 %0, %1;" : "=f"(y) : "f"(x));
    return y;
}

// -------- attn inner-loop helpers --------
// QK score for one key j against both queries (16-dim dot each).
__device__ __forceinline__ void qk_score(const ull* qa, const ull* qb,
                                         const float4* kv, int j,
                                         float& sa, float& sb) {
    const longlong2* kj = (const longlong2*)&kv[j * 4];
    longlong2 k0 = kj[0], k1 = kj[1];
    ull a0 = fmul2(qa[0], (ull)k0.x);
    ull b0 = fmul2(qb[0], (ull)k0.x);
    ull a1 = fmul2(qa[1], (ull)k0.y);
    ull b1 = fmul2(qb[1], (ull)k0.y);
    a0 = ffma2(qa[2], (ull)k1.x, a0);
    b0 = ffma2(qb[2], (ull)k1.x, b0);
    a1 = ffma2(qa[3], (ull)k1.y, a1);
    b1 = ffma2(qb[3], (ull)k1.y, b1);
    longlong2 k2 = kj[2], k3 = kj[3];
    a0 = ffma2(qa[4], (ull)k2.x, a0);
    b0 = ffma2(qb[4], (ull)k2.x, b0);
    a1 = ffma2(qa[5], (ull)k2.y, a1);
    b1 = ffma2(qb[5], (ull)k2.y, b1);
    a0 = ffma2(qa[6], (ull)k3.x, a0);
    b0 = ffma2(qb[6], (ull)k3.x, b0);
    a1 = ffma2(qa[7], (ull)k3.y, a1);
    b1 = ffma2(qb[7], (ull)k3.y, b1);
    float2 ua = upk2(a0), va = upk2(a1);
    float2 ub = upk2(b0), vb = upk2(b1);
    sa = (ua.x + ua.y) + (va.x + va.y);
    sb = (ub.x + ub.y) + (vb.x + vb.y);
}

// o += p * V[j], both queries
__device__ __forceinline__ void pv_acc(float pA, float pB,
                                       const float4* kv, int j,
                                       ull* oa, ull* ob) {
    ull p2a = pk2(pA, pA), p2b = pk2(pB, pB);
    const longlong2* vj = (const longlong2*)&kv[128 + j * 4];
    longlong2 v0 = vj[0], v1 = vj[1];
    oa[0] = ffma2(p2a, (ull)v0.x, oa[0]);
    ob[0] = ffma2(p2b, (ull)v0.x, ob[0]);
    oa[1] = ffma2(p2a, (ull)v0.y, oa[1]);
    ob[1] = ffma2(p2b, (ull)v0.y, ob[1]);
    longlong2 v2 = vj[2], v3 = vj[3];
    oa[2] = ffma2(p2a, (ull)v1.x, oa[2]);
    ob[2] = ffma2(p2b, (ull)v1.x, ob[2]);
    oa[3] = ffma2(p2a, (ull)v1.y, oa[3]);
    ob[3] = ffma2(p2b, (ull)v1.y, ob[3]);
    oa[4] = ffma2(p2a, (ull)v2.x, oa[4]);
    ob[4] = ffma2(p2b, (ull)v2.x, ob[4]);
    oa[5] = ffma2(p2a, (ull)v2.y, oa[5]);
    ob[5] = ffma2(p2b, (ull)v2.y, ob[5]);
    oa[6] = ffma2(p2a, (ull)v3.x, oa[6]);
    ob[6] = ffma2(p2b, (ull)v3.x, ob[6]);
    oa[7] = ffma2(p2a, (ull)v3.y, oa[7]);
    ob[7] = ffma2(p2b, (ull)v3.y, ob[7]);
}

__device__ __forceinline__ void rescale(float tm, float& m, float& l, ull* o) {
    if (tm > m) {
        float corr = ex2(m - tm);      // 0 on first chunk
        l *= corr;
        ull c2 = pk2(corr, corr);
#pragma unroll
        for (int i = 0; i < 8; i++) o[i] = fmul2(o[i], c2);
        m = tm;
    }
}

// ============================================================================
// Kernel 1: fused QKV projection, f32x2-packed. 32 rows/block, grid (256, 3).
// ============================================================================
__global__ __launch_bounds__(256) void qkv_kernel(
    const float* __restrict__ X,
    const float* __restrict__ Wq,
    const float* __restrict__ Wk,
    const float* __restrict__ Wv)
{
    __shared__ float Xs[32][128];
    int which = blockIdx.y;
    const float* W = (which == 0) ? Wq : ((which == 1) ? Wk : Wv);
    float* out = (which == 0) ? g_Q : ((which == 1) ? g_K : g_V);
    float scale = (which == 0) ? (0.08838834764831845f * 1.4426950408889634f) : 1.0f;

    int row0 = blockIdx.x * 32;
    const float4* X4 = (const float4*)(X + row0 * 128);
    float4* Xs4 = (float4*)&Xs[0][0];
#pragma unroll
    for (int i = 0; i < 4; i++)
        Xs4[threadIdx.x + i * 256] = X4[threadIdx.x + i * 256];
    __syncthreads();

    int c4 = threadIdx.x & 31;
    int rg = threadIdx.x >> 5;

    ull acc01[4], acc23[4];
#pragma unroll
    for (int i = 0; i < 4; i++) { acc01[i] = 0ull; acc23[i] = 0ull; }

    const longlong2* WL = (const longlong2*)W;
    for (int d0 = 0; d0 < 128; d0 += 4) {
        longlong2 w0 = WL[(d0 + 0) * 32 + c4];
        longlong2 w1 = WL[(d0 + 1) * 32 + c4];
        longlong2 w2 = WL[(d0 + 2) * 32 + c4];
        longlong2 w3 = WL[(d0 + 3) * 32 + c4];
#pragma unroll
        for (int i = 0; i < 4; i++) {
            float4 a = *(const float4*)&Xs[rg * 4 + i][d0];
            ull ax = pk2(a.x, a.x), ay = pk2(a.y, a.y);
            ull az = pk2(a.z, a.z), aw = pk2(a.w, a.w);
            acc01[i] = ffma2(ax, (ull)w0.x, acc01[i]);
            acc23[i] = ffma2(ax, (ull)w0.y, acc23[i]);
            acc01[i] = ffma2(ay, (ull)w1.x, acc01[i]);
            acc23[i] = ffma2(ay, (ull)w1.y, acc23[i]);
            acc01[i] = ffma2(az, (ull)w2.x, acc01[i]);
            acc23[i] = ffma2(az, (ull)w2.y, acc23[i]);
            acc01[i] = ffma2(aw, (ull)w3.x, acc01[i]);
            acc23[i] = ffma2(aw, (ull)w3.y, acc23[i]);
        }
    }

    int col = c4 * 4;
    int h = col >> 4;
    int j = col & 15;
#pragma unroll
    for (int i = 0; i < 4; i++) {
        int row = row0 + rg * 4 + i;
        int b = row >> 11;
        int s = row & 2047;
        float2 lo = upk2(acc01[i]), hi = upk2(acc23[i]);
        float4 v = make_float4(lo.x * scale, lo.y * scale, hi.x * scale, hi.y * scale);
        *(float4*)&out[(((b * 8 + h) * NS + s) * 16) + j] = v;
    }
}

// ============================================================================
// Kernel 2: merged lin_w transpose + key compaction (saves a launch).
// Blocks 0..63: transpose. Blocks 64..67: compact batch (blk-64), warp 0 only.
// ============================================================================
__global__ void prep_compact_kernel(const float* __restrict__ lw,
                                    const int* __restrict__ mask) {
    if (blockIdx.x < 64) {
        int t = blockIdx.x * 256 + threadIdx.x;
        int d = t >> 7, c = t & 127;
        g_LWT[t] = lw[c * 128 + d];
        return;
    }
    if (threadIdx.x >= 32) return;
    int b = blockIdx.x - 64;
    int lane = threadIdx.x;
    const int* m = mask + b * NS;
    int base = 0;
    for (int k0 = 0; k0 < NS; k0 += 32) {
        int v = (m[k0 + lane] != 0);
        unsigned bal = __ballot_sync(0xffffffffu, v);
        int pos = base + __popc(bal & ((1u << lane) - 1u));
        if (v) g_list[b][pos] = k0 + lane;
        base += __popc(bal);
    }
    if (base == 0) {
        for (int i = lane; i < NS; i += 32) g_list[b][i] = i;
        base = NS;
    }
    int padded = (base + 31) & ~31;              // pad to tile of 32
    for (int i = base + lane; i < padded; i += 32) g_list[b][i] = 0;
    if (lane == 0) g_cnt[b] = base;
}

// ============================================================================
// Kernel 3: flash attention, compacted keys, split-K x4, 2 queries/thread.
// Chunked 2-pass (8-key chunks) -> no big score arrays -> <=128 regs
// -> 4 blocks/SM. Key tile = 32 in smem (one sync pair per 32 keys).
// grid (8, 32, 4).
// ============================================================================
__global__ __launch_bounds__(128, 4) void attn_kernel() {
    __shared__ float4 KV[256];   // [0..127] K (32 keys x 16f), [128..255] V
    __shared__ int lst[512];     // this split's compacted key indices

    int bh = blockIdx.y;
    int b = bh >> 3;
    int sp = blockIdx.z;
    int tid = threadIdx.x;

    int cnt = g_cnt[b];
    int ntiles = (cnt + 31) >> 5;
    int tps = (ntiles + NSPLIT - 1) >> 2;
    int t0 = sp * tps;
    int t1 = min(ntiles, t0 + tps);

    int ra = blockIdx.x * 256 + tid;          // query a
    int pa = (sp * NBH + bh) * NS + ra;
    int pb = pa + 128;                        // query a+128

    if (t0 >= t1) {                           // empty split (block-uniform)
        float4 z = make_float4(0.f, 0.f, 0.f, 0.f);
        g_Pml[pa] = make_float2(-1e30f, 0.f);
        g_Pml[pb] = make_float2(-1e30f, 0.f);
        float4* Pa = &g_Po[(size_t)pa * 4];
        float4* Pb = &g_Po[(size_t)pb * 4];
#pragma unroll
        for (int i = 0; i < 4; i++) { Pa[i] = z; Pb[i] = z; }
        return;
    }

    for (int i = tid; i < (t1 - t0) * 32; i += 128)
        lst[i] = g_list[b][t0 * 32 + i];

    ull qa[8], qb[8];
    {
        const longlong2* Q2a = (const longlong2*)(g_Q + ((size_t)bh * NS + ra) * 16);
        const longlong2* Q2b = Q2a + 128 * 4;
#pragma unroll
        for (int i = 0; i < 4; i++) {
            longlong2 ta = Q2a[i], tb = Q2b[i];
            qa[2 * i] = (ull)ta.x; qa[2 * i + 1] = (ull)ta.y;
            qb[2 * i] = (ull)tb.x; qb[2 * i + 1] = (ull)tb.y;
        }
    }
    __syncthreads();

    float ma = -1e30f, la = 0.f, mb = -1e30f, lb = 0.f;
    ull oa[8], ob[8];
#pragma unroll
    for (int i = 0; i < 8; i++) { oa[i] = 0ull; ob[i] = 0ull; }

    const float4* Kb4 = (const float4*)(g_K + (size_t)bh * NS * 16);
    const float4* Vb4 = (const float4*)(g_V + (size_t)bh * NS * 16);

    int lrow = tid >> 2, lpart = tid & 3;     // tile-load role

    for (int t = t0; t < t1; t++) {
        {
            int kidx = lst[(t - t0) * 32 + lrow];
            KV[lrow * 4 + lpart]       = Kb4[(size_t)kidx * 4 + lpart];
            KV[128 + lrow * 4 + lpart] = Vb4[(size_t)kidx * 4 + lpart];
        }
        __syncthreads();

        int jlim = min(32, cnt - (t << 5));   // partial only for global last tile
        if (jlim == 32) {
#pragma unroll
            for (int c = 0; c < 4; c++) {     // 4 chunks of 8 keys
                float sva[8], svb[8];
#pragma unroll
                for (int j = 0; j < 8; j++)
                    qk_score(qa, qb, KV, c * 8 + j, sva[j], svb[j]);

                float tma = sva[0], tmb = svb[0];
#pragma unroll
                for (int j = 1; j < 8; j++) {
                    tma = fmaxf(tma, sva[j]);
                    tmb = fmaxf(tmb, svb[j]);
                }
                rescale(tma, ma, la, oa);
                rescale(tmb, mb, lb, ob);

#pragma unroll
                for (int j = 0; j < 8; j++) {
                    float pA = ex2(sva[j] - ma);
                    float pB = ex2(svb[j] - mb);
                    la += pA;
                    lb += pB;
                    pv_acc(pA, pB, KV, c * 8 + j, oa, ob);
                }
            }
        } else {
            for (int j = 0; j < jlim; j++) {  // ragged tail, once per block max
                float sa, sb;
                qk_score(qa, qb, KV, j, sa, sb);
                rescale(sa, ma, la, oa);
                rescale(sb, mb, lb, ob);
                float pA = ex2(sa - ma);
                float pB = ex2(sb - mb);
                la += pA;
                lb += pB;
                pv_acc(pA, pB, KV, j, oa, ob);
            }
        }
        __syncthreads();
    }

    g_Pml[pa] = make_float2(ma, la);
    g_Pml[pb] = make_float2(mb, lb);
    float4* Pa = &g_Po[(size_t)pa * 4];
    float4* Pb = &g_Po[(size_t)pb * 4];
#pragma unroll
    for (int i = 0; i < 4; i++) {
        float2 xa = upk2(oa[2 * i]), ya = upk2(oa[2 * i + 1]);
        float2 xb = upk2(ob[2 * i]), yb = upk2(ob[2 * i + 1]);
        Pa[i] = make_float4(xa.x, xa.y, ya.x, ya.y);
        Pb[i] = make_float4(xb.x, xb.y, yb.x, yb.y);
    }
}

// ============================================================================
// Kernel 3b: combine split-K partials -> g_O. One thread per query.
// ============================================================================
__global__ __launch_bounds__(256) void combine_kernel() {
    int q = blockIdx.x * 256 + threadIdx.x;

    float2 ml[NSPLIT];
    float M = -1e30f;
#pragma unroll
    for (int s = 0; s < NSPLIT; s++) {
        ml[s] = g_Pml[s * NQ + q];
        M = fmaxf(M, ml[s].x);
    }
    float l = 0.f;
    float4 o0 = make_float4(0, 0, 0, 0), o1 = o0, o2v = o0, o3 = o0;
#pragma unroll
    for (int s = 0; s < NSPLIT; s++) {
        float w = ex2(ml[s].x - M);
        l += ml[s].y * w;
        const float4* P = &g_Po[((size_t)s * NQ + q) * 4];
        float4 p0 = P[0], p1 = P[1], p2 = P[2], p3 = P[3];
        o0.x += p0.x * w; o0.y += p0.y * w; o0.z += p0.z * w; o0.w += p0.w * w;
        o1.x += p1.x * w; o1.y += p1.y * w; o1.z += p1.z * w; o1.w += p1.w * w;
        o2v.x += p2.x * w; o2v.y += p2.y * w; o2v.z += p2.z * w; o2v.w += p2.w * w;
        o3.x += p3.x * w; o3.y += p3.y * w; o3.z += p3.z * w; o3.w += p3.w * w;
    }
    float inv = 1.0f / l;
    float4* O = (float4*)(g_O + (size_t)q * 16);
    O[0] = make_float4(o0.x * inv, o0.y * inv, o0.z * inv, o0.w * inv);
    O[1] = make_float4(o1.x * inv, o1.y * inv, o1.z * inv, o1.w * inv);
    O[2] = make_float4(o2v.x * inv, o2v.y * inv, o2v.z * inv, o2v.w * inv);
    O[3] = make_float4(o3.x * inv, o3.y * inv, o3.z * inv, o3.w * inv);
}

// ============================================================================
// Kernel 4: output projection, f32x2-packed. 32 rows/block, grid 256.
// ============================================================================
__global__ __launch_bounds__(256) void proj_kernel(
    const float* __restrict__ bias, float* __restrict__ out)
{
    __shared__ float Xs[32][128];
    int row0 = blockIdx.x * 32;

#pragma unroll
    for (int ii = 0; ii < 4; ii++) {
        int i = threadIdx.x + ii * 256;
        int rr = i >> 5, cc4 = i & 31;
        int row = row0 + rr;
        int b = row >> 11, s = row & 2047;
        int col = cc4 * 4;
        int hh = c_ord[col >> 4];
        int j = col & 15;
        *(float4*)&Xs[rr][col] =
            *(const float4*)&g_O[(((b * 8 + hh) * NS + s) * 16) + j];
    }
    __syncthreads();

    int c4 = threadIdx.x & 31;
    int rg = threadIdx.x >> 5;

    float4 bb = ((const float4*)bias)[c4];
    ull acc01[4], acc23[4];
#pragma unroll
    for (int i = 0; i < 4; i++) {
        acc01[i] = pk2(bb.x, bb.y);
        acc23[i] = pk2(bb.z, bb.w);
    }

    const longlong2* WL = (const longlong2*)g_LWT;
    for (int d0 = 0; d0 < 128; d0 += 4) {
        longlong2 w0 = WL[(d0 + 0) * 32 + c4];
        longlong2 w1 = WL[(d0 + 1) * 32 + c4];
        longlong2 w2 = WL[(d0 + 2) * 32 + c4];
        longlong2 w3 = WL[(d0 + 3) * 32 + c4];
#pragma unroll
        for (int i = 0; i < 4; i++) {
            float4 a = *(const float4*)&Xs[rg * 4 + i][d0];
            ull ax = pk2(a.x, a.x), ay = pk2(a.y, a.y);
            ull az = pk2(a.z, a.z), aw = pk2(a.w, a.w);
            acc01[i] = ffma2(ax, (ull)w0.x, acc01[i]);
            acc23[i] = ffma2(ax, (ull)w0.y, acc23[i]);
            acc01[i] = ffma2(ay, (ull)w1.x, acc01[i]);
            acc23[i] = ffma2(ay, (ull)w1.y, acc23[i]);
            acc01[i] = ffma2(az, (ull)w2.x, acc01[i]);
            acc23[i] = ffma2(az, (ull)w2.y, acc23[i]);
            acc01[i] = ffma2(aw, (ull)w3.x, acc01[i]);
            acc23[i] = ffma2(aw, (ull)w3.y, acc23[i]);
        }
    }

#pragma unroll
    for (int i = 0; i < 4; i++) {
        int row = row0 + rg * 4 + i;
        float2 lo = upk2(acc01[i]), hi = upk2(acc23[i]);
        ((float4*)out)[row * 32 + c4] = make_float4(lo.x, lo.y, hi.x, hi.y);
    }
}

// ============================================================================
extern "C" void kernel_launch(void* const* d_in, const int* in_sizes, int n_in,
                              void* d_out, int out_size) {
    const float* X    = (const float*)d_in[0];
    const int*   mask = (const int*)d_in[1];
    const float* Wq   = (const float*)d_in[2];
    const float* Wk   = (const float*)d_in[3];
    const float* Wv   = (const float*)d_in[4];
    const float* lw   = (const float*)d_in[5];
    const float* lb   = (const float*)d_in[6];
    float* out = (float*)d_out;

    qkv_kernel<<<dim3(256, 3), 256>>>(X, Wq, Wk, Wv);
    prep_compact_kernel<<<68, 256>>>(lw, mask);
    attn_kernel<<<dim3(8, 32, NSPLIT), 128>>>();
    combine_kernel<<<NQ / 256, 256>>>();
    proj_kernel<<<256, 256>>>(lb, out);
}